// round 4
// baseline (speedup 1.0000x reference)
#include <cuda_runtime.h>
#include <cuda_bf16.h>
#include <cstdint>

#define B_   64
#define T_   512
#define E_   512
#define H_   1024
#define G3   3072
#define NCTA 64
#define HC   16

// Single extern shared symbol for the whole TU.
extern __shared__ unsigned char smem_raw[];

// ---------------------------------------------------------------------------
// Device scratch (zero-initialized at load; no runtime allocation)
// ---------------------------------------------------------------------------
__device__ float g_xproj[(size_t)B_ * T_ * G3];              // input projections
__device__ __align__(128) unsigned g_hf[2][32768];           // ping-pong h, A-fragment order (128KB each)
__device__ float    g_acc[B_];                               // head partials
__device__ unsigned g_cnt;                                   // barrier counter
__device__ unsigned g_gen;                                   // barrier generation

// ---------------------------------------------------------------------------
// Helpers
// ---------------------------------------------------------------------------
__device__ __forceinline__ float tf32r(float x) {
    unsigned u;
    asm("cvt.rna.tf32.f32 %0, %1;" : "=r"(u) : "f"(x));
    return __uint_as_float(u);
}

__device__ __forceinline__ void mma_tf32(float c[4], const unsigned a[4],
                                         unsigned b0, unsigned b1) {
    asm volatile(
        "mma.sync.aligned.m16n8k8.row.col.f32.tf32.tf32.f32 "
        "{%0,%1,%2,%3}, {%4,%5,%6,%7}, {%8,%9}, {%0,%1,%2,%3};\n"
        : "+f"(c[0]), "+f"(c[1]), "+f"(c[2]), "+f"(c[3])
        : "r"(a[0]), "r"(a[1]), "r"(a[2]), "r"(a[3]), "r"(b0), "r"(b1));
}

__device__ __forceinline__ void mma_bf16(float* c, unsigned a0, unsigned a1,
                                         unsigned a2, unsigned a3,
                                         unsigned b0, unsigned b1) {
    asm volatile(
        "mma.sync.aligned.m16n8k16.row.col.f32.bf16.bf16.f32 "
        "{%0,%1,%2,%3}, {%4,%5,%6,%7}, {%8,%9}, {%0,%1,%2,%3};\n"
        : "+f"(c[0]), "+f"(c[1]), "+f"(c[2]), "+f"(c[3])
        : "r"(a0), "r"(a1), "r"(a2), "r"(a3), "r"(b0), "r"(b1));
}

__device__ __forceinline__ float sigf(float x) {
    return 1.0f / (1.0f + __expf(-x));
}

// Grid barrier: acq/rel atomics only — no membar.gl (no L1 flush).
__device__ __forceinline__ void grid_sync_dev() {
    __syncthreads();
    if (threadIdx.x == 0) {
        unsigned my;
        asm volatile("ld.acquire.gpu.global.u32 %0, [%1];"
                     : "=r"(my) : "l"(&g_gen));
        unsigned a;
        asm volatile("atom.acq_rel.gpu.global.add.u32 %0, [%1], 1;"
                     : "=r"(a) : "l"(&g_cnt));
        if (a == NCTA - 1) {
            asm volatile("st.relaxed.gpu.global.u32 [%0], 0;" :: "l"(&g_cnt));
            asm volatile("red.release.gpu.global.add.u32 [%0], 1;" :: "l"(&g_gen));
        } else {
            unsigned cur;
            do {
                asm volatile("ld.acquire.gpu.global.u32 %0, [%1];"
                             : "=r"(cur) : "l"(&g_gen));
            } while (cur == my);
        }
    }
    __syncthreads();
}

__device__ __forceinline__ void mbar_wait_parity(unsigned mbar, unsigned phase) {
    unsigned done;
    do {
        asm volatile(
            "{\n\t.reg .pred p;\n\t"
            "mbarrier.try_wait.parity.acquire.cta.shared::cta.b64 p, [%1], %2, 0x989680;\n\t"
            "selp.b32 %0, 1, 0, p;\n\t}"
            : "=r"(done) : "r"(mbar), "r"(phase) : "memory");
    } while (!done);
}

// ---------------------------------------------------------------------------
// Phase 1: x_proj = input @ W_ih^T + b_ih   (TF32 mma, unchanged from R3)
// ---------------------------------------------------------------------------
__global__ void __launch_bounds__(256)
xproj_kernel(const float* __restrict__ A, const float* __restrict__ W,
             const float* __restrict__ bih, const int* __restrict__ seqlen)
{
    const int tm = blockIdx.y, tn = blockIdx.x;
    const int b  = (tm << 7) >> 9;
    const int t0 = (tm << 7) & 511;
    if (t0 >= seqlen[b]) return;

    float* smem = (float*)smem_raw;
    float* As = smem;
    float* Bs = smem + 2 * 128 * 36;

    const int tid  = threadIdx.x;
    const int lane = tid & 31, wid = tid >> 5;
    const int warpM = wid >> 2, warpN = wid & 3;

    const float* Ag = A + (size_t)(tm * 128) * E_;
    const float* Bg = W + (size_t)(tn * 128) * E_;

    float acc[4][4][4];
#pragma unroll
    for (int i = 0; i < 4; i++)
#pragma unroll
        for (int j = 0; j < 4; j++)
#pragma unroll
            for (int k = 0; k < 4; k++) acc[i][j][k] = 0.0f;

#pragma unroll
    for (int i = 0; i < 4; i++) {
        int f = tid + i * 256;
        int r = f >> 3, c4 = (f & 7) << 2;
        float4 va = *(const float4*)(Ag + (size_t)r * E_ + c4);
        float4 vb = *(const float4*)(Bg + (size_t)r * E_ + c4);
        float* da = As + r * 36 + c4;
        float* db = Bs + r * 36 + c4;
        da[0] = tf32r(va.x); da[1] = tf32r(va.y); da[2] = tf32r(va.z); da[3] = tf32r(va.w);
        db[0] = tf32r(vb.x); db[1] = tf32r(vb.y); db[2] = tf32r(vb.z); db[3] = tf32r(vb.w);
    }
    __syncthreads();

    for (int ko = 0; ko < 16; ko++) {
        float4 pa[4], pb[4];
        if (ko < 15) {
            int kb = (ko + 1) * 32;
#pragma unroll
            for (int i = 0; i < 4; i++) {
                int f = tid + i * 256;
                int r = f >> 3, c4 = (f & 7) << 2;
                pa[i] = *(const float4*)(Ag + (size_t)r * E_ + kb + c4);
                pb[i] = *(const float4*)(Bg + (size_t)r * E_ + kb + c4);
            }
        }
        const float* Ab = As + (ko & 1) * 128 * 36;
        const float* Bb = Bs + (ko & 1) * 128 * 36;
#pragma unroll
        for (int kk = 0; kk < 32; kk += 8) {
            unsigned a[4][4];
            const int kc = kk + (lane & 3);
#pragma unroll
            for (int mt = 0; mt < 4; mt++) {
                int r = warpM * 64 + mt * 16 + (lane >> 2);
                a[mt][0] = __float_as_uint(Ab[r * 36 + kc]);
                a[mt][1] = __float_as_uint(Ab[(r + 8) * 36 + kc]);
                a[mt][2] = __float_as_uint(Ab[r * 36 + kc + 4]);
                a[mt][3] = __float_as_uint(Ab[(r + 8) * 36 + kc + 4]);
            }
#pragma unroll
            for (int nt = 0; nt < 4; nt++) {
                int nr = warpN * 32 + nt * 8 + (lane >> 2);
                unsigned b0 = __float_as_uint(Bb[nr * 36 + kc]);
                unsigned b1 = __float_as_uint(Bb[nr * 36 + kc + 4]);
#pragma unroll
                for (int mt = 0; mt < 4; mt++) mma_tf32(acc[mt][nt], a[mt], b0, b1);
            }
        }
        if (ko < 15) {
            float* Ad = As + ((ko + 1) & 1) * 128 * 36;
            float* Bd = Bs + ((ko + 1) & 1) * 128 * 36;
#pragma unroll
            for (int i = 0; i < 4; i++) {
                int f = tid + i * 256;
                int r = f >> 3, c4 = (f & 7) << 2;
                float* da = Ad + r * 36 + c4;
                float* db = Bd + r * 36 + c4;
                da[0] = tf32r(pa[i].x); da[1] = tf32r(pa[i].y);
                da[2] = tf32r(pa[i].z); da[3] = tf32r(pa[i].w);
                db[0] = tf32r(pb[i].x); db[1] = tf32r(pb[i].y);
                db[2] = tf32r(pb[i].z); db[3] = tf32r(pb[i].w);
            }
        }
        __syncthreads();
    }

#pragma unroll
    for (int nt = 0; nt < 4; nt++) {
        int cg = tn * 128 + warpN * 32 + nt * 8 + 2 * (lane & 3);
        float bv0 = bih[cg], bv1 = bih[cg + 1];
#pragma unroll
        for (int mt = 0; mt < 4; mt++) {
            int rg = tm * 128 + warpM * 64 + mt * 16 + (lane >> 2);
            float2 v0 = make_float2(acc[mt][nt][0] + bv0, acc[mt][nt][1] + bv1);
            float2 v1 = make_float2(acc[mt][nt][2] + bv0, acc[mt][nt][3] + bv1);
            *(float2*)&g_xproj[(size_t)rg * G3 + cg]       = v0;
            *(float2*)&g_xproj[(size_t)(rg + 8) * G3 + cg] = v1;
        }
    }
}

// ---------------------------------------------------------------------------
// Phase 2: persistent GRU, 64 CTAs x 256 thr.
// h lives in GMEM in mma-A-fragment order: frag[kt][mtile][lane][4 u32],
// offset = ((kt*4+mtile)*32+lane)*16B. Per step: 4x cp.async.bulk (2 mbarrier
// halves) broadcast it to SMEM; A loaded with plain ld.shared.v4 (conflict-
// free); W_hh B-fragments SMEM-resident; acq/rel grid barrier.
// ---------------------------------------------------------------------------
#define WOFF    98304                       // W fragment region bytes
#define MBAROFF (98304 + 131072)
#define SMEM2   (98304 + 131072 + 32)

__global__ void __launch_bounds__(256)
gru_kernel(const int* __restrict__ seqlen, const float* __restrict__ W_hh,
           const float* __restrict__ b_hh, const float* __restrict__ W_out,
           const float* __restrict__ b_out, float* __restrict__ out)
{
    unsigned char* smem = smem_raw;
    uint2* Wbuf = (uint2*)smem;                 // [2][3][64][32] uint2
    float* hp   = (float*)(smem + WOFF);        // alias over h region after mma

    const int c    = blockIdx.x;
    const int tid  = threadIdx.x;
    const int lane = tid & 31, wid = tid >> 5;
    const int mtile = wid >> 1, nhalf = wid & 1;
    const int m0 = mtile * 16;

    const unsigned smem_u32 = (unsigned)__cvta_generic_to_shared(smem);
    const unsigned hs_u32   = smem_u32 + WOFF;
    const unsigned mb0      = smem_u32 + MBAROFF;
    const unsigned mb1      = mb0 + 8;

    // ---- init mbarriers ----------------------------------------------------
    if (tid == 0) {
        asm volatile("mbarrier.init.shared.b64 [%0], 1;" :: "r"(mb0) : "memory");
        asm volatile("mbarrier.init.shared.b64 [%0], 1;" :: "r"(mb1) : "memory");
        asm volatile("fence.proxy.async.shared::cta;" ::: "memory");
    }

    // ---- pre-permute W_hh slice into B-fragment order (bf16) ---------------
    for (int i = tid; i < 12288; i += 256) {
        int nh = i / 6144;
        int r  = i - nh * 6144;
        int nt = r / 2048;
        int r2 = r - nt * 2048;
        int kt = r2 >> 5, li = r2 & 31;
        int o  = nh * 24 + nt * 8 + (li >> 2);
        int grow = (o >> 4) * H_ + c * HC + (o & 15);
        int k0 = kt * 16 + (li & 3) * 2;
        const float* wr = W_hh + (size_t)grow * H_;
        __nv_bfloat162 p0 = __floats2bfloat162_rn(wr[k0],     wr[k0 + 1]);
        __nv_bfloat162 p1 = __floats2bfloat162_rn(wr[k0 + 8], wr[k0 + 9]);
        uint2 v;
        v.x = *reinterpret_cast<unsigned*>(&p0);
        v.y = *reinterpret_cast<unsigned*>(&p1);
        Wbuf[i] = v;
    }

    // ---- pointwise identity: batch b_mine, 4 consecutive units -------------
    const int b_mine = tid >> 2;
    const int ubase  = (tid & 3) << 2;
    const int sl     = seqlen[b_mine];
    float bh[3][4];
#pragma unroll
    for (int g = 0; g < 3; g++)
#pragma unroll
        for (int j = 0; j < 4; j++)
            bh[g][j] = b_hh[g * H_ + c * HC + ubase + j];
    float hv[4] = {0.f, 0.f, 0.f, 0.f};

    // fragment-slot offset (u32 units) this thread writes each step
    const int r_b   = b_mine & 15;
    const int mt_b  = b_mine >> 4;
    const int lane_b = ((r_b & 7) << 2) + ((ubase >> 1) & 2);
    const int reg_b  = ((ubase & 8) ? 2 : 0) + (r_b >> 3);
    const unsigned fo = (((unsigned)(c * 4 + mt_b) * 32 + lane_b) << 2) + reg_b;

    // zero my slots of frag buffer 0; zero head accumulators
    {
        unsigned* p = &g_hf[0][fo];
        asm volatile("st.global.cg.u32 [%0], 0;" :: "l"(p));
        asm volatile("st.global.cg.u32 [%0], 0;" :: "l"(p + 4));
    }
    if (c == 0 && tid < B_) g_acc[tid] = 0.f;

    grid_sync_dev();

    // ---- per-lane compute constants ----------------------------------------
    const unsigned abase = hs_u32 + (unsigned)(mtile * 512 + lane * 16);
    const unsigned wbase = smem_u32 + (unsigned)((nhalf * 3 * 64) * 256 + lane * 8);

    for (int t = 0; t < T_; t++) {
        const int rb = t & 1, wb = rb ^ 1;
        const unsigned ph = (unsigned)(t & 1);

        // ---- issue bulk h broadcast: 2 halves x 2 chunks of 32KB -----------
        if (tid == 0) {
            const char* src = (const char*)&g_hf[rb][0];
            asm volatile("fence.proxy.async;" ::: "memory");
            asm volatile("mbarrier.arrive.expect_tx.shared.b64 _, [%0], %1;"
                         :: "r"(mb0), "r"(65536u) : "memory");
            asm volatile("cp.async.bulk.shared::cluster.global.mbarrier::complete_tx::bytes "
                         "[%0], [%1], %2, [%3];"
                         :: "r"(hs_u32), "l"(src), "r"(32768u), "r"(mb0) : "memory");
            asm volatile("cp.async.bulk.shared::cluster.global.mbarrier::complete_tx::bytes "
                         "[%0], [%1], %2, [%3];"
                         :: "r"(hs_u32 + 32768u), "l"(src + 32768), "r"(32768u), "r"(mb0) : "memory");
            asm volatile("mbarrier.arrive.expect_tx.shared.b64 _, [%0], %1;"
                         :: "r"(mb1), "r"(65536u) : "memory");
            asm volatile("cp.async.bulk.shared::cluster.global.mbarrier::complete_tx::bytes "
                         "[%0], [%1], %2, [%3];"
                         :: "r"(hs_u32 + 65536u), "l"(src + 65536), "r"(32768u), "r"(mb1) : "memory");
            asm volatile("cp.async.bulk.shared::cluster.global.mbarrier::complete_tx::bytes "
                         "[%0], [%1], %2, [%3];"
                         :: "r"(hs_u32 + 98304u), "l"(src + 98304), "r"(32768u), "r"(mb1) : "memory");
        }

        // ---- xproj loads (DRAM, independent of h) ---------------------------
        const bool active = t < sl;
        float4 xr, xz, xn;
        if (active) {
            size_t base = ((size_t)b_mine * T_ + t) * G3 + c * HC + ubase;
            xr = __ldcg((const float4*)&g_xproj[base]);
            xz = __ldcg((const float4*)&g_xproj[base + H_]);
            xn = __ldcg((const float4*)&g_xproj[base + 2 * H_]);
        }

        float acc[2][3][4];
#pragma unroll
        for (int p = 0; p < 2; p++)
#pragma unroll
            for (int nt = 0; nt < 3; nt++)
#pragma unroll
                for (int j = 0; j < 4; j++) acc[p][nt][j] = 0.f;

        // ---- half 0: kt 0..31 ----------------------------------------------
        mbar_wait_parity(mb0, ph);
#pragma unroll
        for (int kt = 0; kt < 32; kt++) {
            unsigned a0, a1, a2, a3;
            asm volatile("ld.shared.v4.u32 {%0,%1,%2,%3}, [%4];"
                         : "=r"(a0), "=r"(a1), "=r"(a2), "=r"(a3)
                         : "r"(abase + kt * 2048u));
            unsigned b00, b01, b10, b11, b20, b21;
            asm volatile("ld.shared.v2.u32 {%0,%1}, [%2];"
                         : "=r"(b00), "=r"(b01) : "r"(wbase + (0 * 64 + kt) * 256u));
            asm volatile("ld.shared.v2.u32 {%0,%1}, [%2];"
                         : "=r"(b10), "=r"(b11) : "r"(wbase + (1 * 64 + kt) * 256u));
            asm volatile("ld.shared.v2.u32 {%0,%1}, [%2];"
                         : "=r"(b20), "=r"(b21) : "r"(wbase + (2 * 64 + kt) * 256u));
            const int p = kt & 1;
            mma_bf16(acc[p][0], a0, a1, a2, a3, b00, b01);
            mma_bf16(acc[p][1], a0, a1, a2, a3, b10, b11);
            mma_bf16(acc[p][2], a0, a1, a2, a3, b20, b21);
        }
        // ---- half 1: kt 32..63 ----------------------------------------------
        mbar_wait_parity(mb1, ph);
#pragma unroll
        for (int kt = 32; kt < 64; kt++) {
            unsigned a0, a1, a2, a3;
            asm volatile("ld.shared.v4.u32 {%0,%1,%2,%3}, [%4];"
                         : "=r"(a0), "=r"(a1), "=r"(a2), "=r"(a3)
                         : "r"(abase + kt * 2048u));
            unsigned b00, b01, b10, b11, b20, b21;
            asm volatile("ld.shared.v2.u32 {%0,%1}, [%2];"
                         : "=r"(b00), "=r"(b01) : "r"(wbase + (0 * 64 + kt) * 256u));
            asm volatile("ld.shared.v2.u32 {%0,%1}, [%2];"
                         : "=r"(b10), "=r"(b11) : "r"(wbase + (1 * 64 + kt) * 256u));
            asm volatile("ld.shared.v2.u32 {%0,%1}, [%2];"
                         : "=r"(b20), "=r"(b21) : "r"(wbase + (2 * 64 + kt) * 256u));
            const int p = kt & 1;
            mma_bf16(acc[p][0], a0, a1, a2, a3, b00, b01);
            mma_bf16(acc[p][1], a0, a1, a2, a3, b10, b11);
            mma_bf16(acc[p][2], a0, a1, a2, a3, b20, b21);
        }
        __syncthreads();   // all mma SMEM reads done; hp alias region now safe

        // ---- dump accumulators to hp[b][o] (stride 52) -----------------------
        {
            int bb = m0 + (lane >> 2);
#pragma unroll
            for (int nt = 0; nt < 3; nt++) {
                int col = nhalf * 24 + nt * 8 + ((lane & 3) << 1);
                hp[bb * 52 + col]           = acc[0][nt][0] + acc[1][nt][0];
                hp[bb * 52 + col + 1]       = acc[0][nt][1] + acc[1][nt][1];
                hp[(bb + 8) * 52 + col]     = acc[0][nt][2] + acc[1][nt][2];
                hp[(bb + 8) * 52 + col + 1] = acc[0][nt][3] + acc[1][nt][3];
            }
        }
        __syncthreads();

        // ---- pointwise GRU update (fp32 carry) -------------------------------
        if (active) {
            const float xrv[4] = {xr.x, xr.y, xr.z, xr.w};
            const float xzv[4] = {xz.x, xz.y, xz.z, xz.w};
            const float xnv[4] = {xn.x, xn.y, xn.z, xn.w};
#pragma unroll
            for (int j = 0; j < 4; j++) {
                float hr = hp[b_mine * 52 + ubase + j];
                float hz = hp[b_mine * 52 + 16 + ubase + j];
                float hn = hp[b_mine * 52 + 32 + ubase + j];
                float r = sigf(xrv[j] + hr + bh[0][j]);
                float z = sigf(xzv[j] + hz + bh[1][j]);
                float n = tanhf(xnv[j] + r * (hn + bh[2][j]));
                hv[j] = (1.0f - z) * n + z * hv[j];
            }
        }
        // write h (bf16, fragment order) for next step's GEMM
        {
            __nv_bfloat162 w0 = __floats2bfloat162_rn(hv[0], hv[1]);
            __nv_bfloat162 w1 = __floats2bfloat162_rn(hv[2], hv[3]);
            unsigned u0 = *reinterpret_cast<unsigned*>(&w0);
            unsigned u1 = *reinterpret_cast<unsigned*>(&w1);
            unsigned* p = &g_hf[wb][fo];
            asm volatile("st.global.cg.u32 [%0], %1;" :: "l"(p), "r"(u0));
            asm volatile("st.global.cg.u32 [%0], %1;" :: "l"(p + 4), "r"(u1));
        }

        grid_sync_dev();
    }

    // ---- head: out[b] = sigmoid(h[b] . W_out + b_out) ------------------------
    float part = 0.f;
#pragma unroll
    for (int j = 0; j < 4; j++)
        part += hv[j] * W_out[c * HC + ubase + j];
    part += __shfl_down_sync(0xffffffffu, part, 1);
    part += __shfl_down_sync(0xffffffffu, part, 2);
    if ((tid & 3) == 0) atomicAdd(&g_acc[b_mine], part);

    grid_sync_dev();

    if (c == 0 && tid < B_) {
        float v = __ldcg(&g_acc[tid]);
        out[tid] = 1.0f / (1.0f + expf(-(v + b_out[0])));
    }
}

// ---------------------------------------------------------------------------
// Launch
// ---------------------------------------------------------------------------
extern "C" void kernel_launch(void* const* d_in, const int* in_sizes, int n_in,
                              void* d_out, int out_size)
{
    const float* input  = (const float*)d_in[0];
    const int*   seqlen = (const int*)  d_in[1];
    const float* W_ih   = (const float*)d_in[2];
    const float* W_hh   = (const float*)d_in[3];
    const float* b_ih   = (const float*)d_in[4];
    const float* b_hh   = (const float*)d_in[5];
    const float* W_out  = (const float*)d_in[6];
    const float* b_out  = (const float*)d_in[7];
    float* out = (float*)d_out;

    const int SMEM1 = 2 * 2 * 128 * 36 * (int)sizeof(float);   // 73728 B

    cudaFuncSetAttribute(xproj_kernel, cudaFuncAttributeMaxDynamicSharedMemorySize, SMEM1);
    cudaFuncSetAttribute(gru_kernel,   cudaFuncAttributeMaxDynamicSharedMemorySize, SMEM2);

    xproj_kernel<<<dim3(24, 256), 256, SMEM1>>>(input, W_ih, b_ih, seqlen);
    gru_kernel<<<NCTA, 256, SMEM2>>>(seqlen, W_hh, b_hh, W_out, b_out, out);
}

// round 5
// speedup vs baseline: 1.1419x; 1.1419x over previous
#include <cuda_runtime.h>
#include <cuda_bf16.h>
#include <cstdint>

#define B_   64
#define T_   512
#define E_   512
#define H_   1024
#define G3   3072
#define NCTA 64
#define HC   16

// Single extern shared symbol for the whole TU.
extern __shared__ unsigned char smem_raw[];

// ---------------------------------------------------------------------------
// Device scratch (zero-initialized at load; no runtime allocation)
// ---------------------------------------------------------------------------
__device__ float g_xproj[(size_t)B_ * T_ * G3];              // input projections
__device__ __align__(128) unsigned g_hf[2][32768];           // ping-pong h, A-fragment order
__device__ float    g_acc[B_];                               // head partials
__device__ unsigned g_cnt;                                   // barrier counter
__device__ unsigned g_gen;                                   // barrier generation

// ---------------------------------------------------------------------------
// Helpers
// ---------------------------------------------------------------------------
__device__ __forceinline__ float tf32r(float x) {
    unsigned u;
    asm("cvt.rna.tf32.f32 %0, %1;" : "=r"(u) : "f"(x));
    return __uint_as_float(u);
}

__device__ __forceinline__ void mma_tf32(float c[4], const unsigned a[4],
                                         unsigned b0, unsigned b1) {
    asm volatile(
        "mma.sync.aligned.m16n8k8.row.col.f32.tf32.tf32.f32 "
        "{%0,%1,%2,%3}, {%4,%5,%6,%7}, {%8,%9}, {%0,%1,%2,%3};\n"
        : "+f"(c[0]), "+f"(c[1]), "+f"(c[2]), "+f"(c[3])
        : "r"(a[0]), "r"(a[1]), "r"(a[2]), "r"(a[3]), "r"(b0), "r"(b1));
}

__device__ __forceinline__ void mma_bf16(float* c, unsigned a0, unsigned a1,
                                         unsigned a2, unsigned a3,
                                         unsigned b0, unsigned b1) {
    asm volatile(
        "mma.sync.aligned.m16n8k16.row.col.f32.bf16.bf16.f32 "
        "{%0,%1,%2,%3}, {%4,%5,%6,%7}, {%8,%9}, {%0,%1,%2,%3};\n"
        : "+f"(c[0]), "+f"(c[1]), "+f"(c[2]), "+f"(c[3])
        : "r"(a0), "r"(a1), "r"(a2), "r"(a3), "r"(b0), "r"(b1));
}

__device__ __forceinline__ float sigf(float x) {
    return 1.0f / (1.0f + __expf(-x));
}

// Grid barrier: acq/rel atomics only (no membar.gl / L1 flush).
__device__ __forceinline__ void grid_sync_dev() {
    __syncthreads();
    if (threadIdx.x == 0) {
        unsigned my;
        asm volatile("ld.acquire.gpu.global.u32 %0, [%1];"
                     : "=r"(my) : "l"(&g_gen));
        unsigned a;
        asm volatile("atom.acq_rel.gpu.global.add.u32 %0, [%1], 1;"
                     : "=r"(a) : "l"(&g_cnt));
        if (a == NCTA - 1) {
            asm volatile("st.relaxed.gpu.global.u32 [%0], 0;" :: "l"(&g_cnt));
            asm volatile("red.release.gpu.global.add.u32 [%0], 1;" :: "l"(&g_gen));
        } else {
            unsigned cur;
            do {
                asm volatile("ld.acquire.gpu.global.u32 %0, [%1];"
                             : "=r"(cur) : "l"(&g_gen));
            } while (cur == my);
        }
    }
    __syncthreads();
}

__device__ __forceinline__ void mbar_wait_parity(unsigned mbar, unsigned phase) {
    unsigned done;
    do {
        asm volatile(
            "{\n\t.reg .pred p;\n\t"
            "mbarrier.try_wait.parity.acquire.cta.shared::cta.b64 p, [%1], %2, 0x989680;\n\t"
            "selp.b32 %0, 1, 0, p;\n\t}"
            : "=r"(done) : "r"(mbar), "r"(phase) : "memory");
    } while (!done);
}

// ---------------------------------------------------------------------------
// Phase 1: x_proj = input @ W_ih^T + b_ih   (TF32 mma, unchanged)
// ---------------------------------------------------------------------------
__global__ void __launch_bounds__(256)
xproj_kernel(const float* __restrict__ A, const float* __restrict__ W,
             const float* __restrict__ bih, const int* __restrict__ seqlen)
{
    const int tm = blockIdx.y, tn = blockIdx.x;
    const int b  = (tm << 7) >> 9;
    const int t0 = (tm << 7) & 511;
    if (t0 >= seqlen[b]) return;

    float* smem = (float*)smem_raw;
    float* As = smem;
    float* Bs = smem + 2 * 128 * 36;

    const int tid  = threadIdx.x;
    const int lane = tid & 31, wid = tid >> 5;
    const int warpM = wid >> 2, warpN = wid & 3;

    const float* Ag = A + (size_t)(tm * 128) * E_;
    const float* Bg = W + (size_t)(tn * 128) * E_;

    float acc[4][4][4];
#pragma unroll
    for (int i = 0; i < 4; i++)
#pragma unroll
        for (int j = 0; j < 4; j++)
#pragma unroll
            for (int k = 0; k < 4; k++) acc[i][j][k] = 0.0f;

#pragma unroll
    for (int i = 0; i < 4; i++) {
        int f = tid + i * 256;
        int r = f >> 3, c4 = (f & 7) << 2;
        float4 va = *(const float4*)(Ag + (size_t)r * E_ + c4);
        float4 vb = *(const float4*)(Bg + (size_t)r * E_ + c4);
        float* da = As + r * 36 + c4;
        float* db = Bs + r * 36 + c4;
        da[0] = tf32r(va.x); da[1] = tf32r(va.y); da[2] = tf32r(va.z); da[3] = tf32r(va.w);
        db[0] = tf32r(vb.x); db[1] = tf32r(vb.y); db[2] = tf32r(vb.z); db[3] = tf32r(vb.w);
    }
    __syncthreads();

    for (int ko = 0; ko < 16; ko++) {
        float4 pa[4], pb[4];
        if (ko < 15) {
            int kb = (ko + 1) * 32;
#pragma unroll
            for (int i = 0; i < 4; i++) {
                int f = tid + i * 256;
                int r = f >> 3, c4 = (f & 7) << 2;
                pa[i] = *(const float4*)(Ag + (size_t)r * E_ + kb + c4);
                pb[i] = *(const float4*)(Bg + (size_t)r * E_ + kb + c4);
            }
        }
        const float* Ab = As + (ko & 1) * 128 * 36;
        const float* Bb = Bs + (ko & 1) * 128 * 36;
#pragma unroll
        for (int kk = 0; kk < 32; kk += 8) {
            unsigned a[4][4];
            const int kc = kk + (lane & 3);
#pragma unroll
            for (int mt = 0; mt < 4; mt++) {
                int r = warpM * 64 + mt * 16 + (lane >> 2);
                a[mt][0] = __float_as_uint(Ab[r * 36 + kc]);
                a[mt][1] = __float_as_uint(Ab[(r + 8) * 36 + kc]);
                a[mt][2] = __float_as_uint(Ab[r * 36 + kc + 4]);
                a[mt][3] = __float_as_uint(Ab[(r + 8) * 36 + kc + 4]);
            }
#pragma unroll
            for (int nt = 0; nt < 4; nt++) {
                int nr = warpN * 32 + nt * 8 + (lane >> 2);
                unsigned b0 = __float_as_uint(Bb[nr * 36 + kc]);
                unsigned b1 = __float_as_uint(Bb[nr * 36 + kc + 4]);
#pragma unroll
                for (int mt = 0; mt < 4; mt++) mma_tf32(acc[mt][nt], a[mt], b0, b1);
            }
        }
        if (ko < 15) {
            float* Ad = As + ((ko + 1) & 1) * 128 * 36;
            float* Bd = Bs + ((ko + 1) & 1) * 128 * 36;
#pragma unroll
            for (int i = 0; i < 4; i++) {
                int f = tid + i * 256;
                int r = f >> 3, c4 = (f & 7) << 2;
                float* da = Ad + r * 36 + c4;
                float* db = Bd + r * 36 + c4;
                da[0] = tf32r(pa[i].x); da[1] = tf32r(pa[i].y);
                da[2] = tf32r(pa[i].z); da[3] = tf32r(pa[i].w);
                db[0] = tf32r(pb[i].x); db[1] = tf32r(pb[i].y);
                db[2] = tf32r(pb[i].z); db[3] = tf32r(pb[i].w);
            }
        }
        __syncthreads();
    }

#pragma unroll
    for (int nt = 0; nt < 4; nt++) {
        int cg = tn * 128 + warpN * 32 + nt * 8 + 2 * (lane & 3);
        float bv0 = bih[cg], bv1 = bih[cg + 1];
#pragma unroll
        for (int mt = 0; mt < 4; mt++) {
            int rg = tm * 128 + warpM * 64 + mt * 16 + (lane >> 2);
            float2 v0 = make_float2(acc[mt][nt][0] + bv0, acc[mt][nt][1] + bv1);
            float2 v1 = make_float2(acc[mt][nt][2] + bv0, acc[mt][nt][3] + bv1);
            *(float2*)&g_xproj[(size_t)rg * G3 + cg]       = v0;
            *(float2*)&g_xproj[(size_t)(rg + 8) * G3 + cg] = v1;
        }
    }
}

// ---------------------------------------------------------------------------
// Phase 2: persistent GRU, 64 CTAs x 256 thr.
// W_hh B-fragments live in REGISTERS (96 u32/thread; warp (q,nh) owns kt range
// q*16..q*16+15 x 24 N-cols). h broadcast: 4x32KB bulk copies + 4 mbarriers;
// warp q waits only chunk q. Partial C reduced across q via SMEM hpq.
// ---------------------------------------------------------------------------
#define HPQOFF  131072
#define MBAROFF (131072 + 53248)
#define SMEM2   (131072 + 53248 + 64)

__global__ void __launch_bounds__(256, 1)
gru_kernel(const int* __restrict__ seqlen, const float* __restrict__ W_hh,
           const float* __restrict__ b_hh, const float* __restrict__ W_out,
           const float* __restrict__ b_out, float* __restrict__ out)
{
    unsigned char* smem = smem_raw;
    float* hpq = (float*)(smem + HPQOFF);       // [4][64][52] partial C

    const int c    = blockIdx.x;
    const int tid  = threadIdx.x;
    const int lane = tid & 31, wid = tid >> 5;
    const int q  = wid >> 1;                    // kt chunk 0..3
    const int nh = wid & 1;                     // N half 0..1

    const unsigned smem_u32 = (unsigned)__cvta_generic_to_shared(smem);
    const unsigned hs_u32   = smem_u32;                     // A stage (128KB)
    const unsigned mbb      = smem_u32 + MBAROFF;           // 4 mbarriers

    // ---- init mbarriers ----------------------------------------------------
    if (tid == 0) {
#pragma unroll
        for (int ch = 0; ch < 4; ch++)
            asm volatile("mbarrier.init.shared.b64 [%0], 1;"
                         :: "r"(mbb + ch * 8) : "memory");
        asm volatile("fence.proxy.async.shared::cta;" ::: "memory");
    }

    // ---- load W_hh B-fragments into registers ------------------------------
    // warp (q,nh), thread lane: fragments for kt = q*16+kt2, nt = 0..2
    unsigned wb0[16][3], wb1[16][3];
    {
        const int nrow = nh * 24 + (lane >> 2);   // base n for nt=0
#pragma unroll
        for (int nt = 0; nt < 3; nt++) {
            int n = nrow + nt * 8;
            int grow = (n >> 4) * H_ + c * HC + (n & 15);
            const float* wr = W_hh + (size_t)grow * H_;
#pragma unroll
            for (int kt2 = 0; kt2 < 16; kt2++) {
                int k0 = (q * 16 + kt2) * 16 + (lane & 3) * 2;
                __nv_bfloat162 p0 = __floats2bfloat162_rn(wr[k0],     wr[k0 + 1]);
                __nv_bfloat162 p1 = __floats2bfloat162_rn(wr[k0 + 8], wr[k0 + 9]);
                wb0[kt2][nt] = *reinterpret_cast<unsigned*>(&p0);
                wb1[kt2][nt] = *reinterpret_cast<unsigned*>(&p1);
            }
        }
    }

    // ---- pointwise identity: batch b_mine, 4 consecutive units -------------
    const int b_mine = tid >> 2;
    const int ubase  = (tid & 3) << 2;
    const int sl     = seqlen[b_mine];
    float bh[3][4];
#pragma unroll
    for (int g = 0; g < 3; g++)
#pragma unroll
        for (int j = 0; j < 4; j++)
            bh[g][j] = b_hh[g * H_ + c * HC + ubase + j];
    float hv[4] = {0.f, 0.f, 0.f, 0.f};

    // fragment-slot offset (u32 units) this thread writes each step
    const int r_b    = b_mine & 15;
    const int mt_b   = b_mine >> 4;
    const int lane_b = ((r_b & 7) << 2) + ((ubase >> 1) & 2);
    const int reg_b  = ((ubase & 8) ? 2 : 0) + (r_b >> 3);
    // NOTE: kt index inside offset: ((kt*4 + mt)*32 + lane)*4 + reg; this
    // thread's h goes to K-position of unit -> kt = (c*HC+...)/16 = c (HC==16)
    const unsigned fo = (((unsigned)(c * 4 + mt_b) * 32 + lane_b) << 2) + reg_b;

    // zero my slots of frag buffer 0; zero head accumulators
    {
        unsigned* p = &g_hf[0][fo];
        asm volatile("st.global.cg.u32 [%0], 0;" :: "l"(p));
        asm volatile("st.global.cg.u32 [%0], 0;" :: "l"(p + 4));
    }
    if (c == 0 && tid < B_) g_acc[tid] = 0.f;

    grid_sync_dev();

    // A-stage read base for this warp: addr = ((kt*4+mt)*32+lane)*16
    const unsigned abase = hs_u32 + (unsigned)(q * 32768 + lane * 16);
    const unsigned mb_q  = mbb + q * 8;

    for (int t = 0; t < T_; t++) {
        const int rb = t & 1, wb = rb ^ 1;
        const unsigned ph = (unsigned)(t & 1);

        // ---- issue chunked bulk h broadcast (4 x 32KB) ----------------------
        if (tid == 0) {
            const char* src = (const char*)&g_hf[rb][0];
            asm volatile("fence.proxy.async;" ::: "memory");
#pragma unroll
            for (int ch = 0; ch < 4; ch++) {
                asm volatile("mbarrier.arrive.expect_tx.shared.b64 _, [%0], %1;"
                             :: "r"(mbb + ch * 8), "r"(32768u) : "memory");
                asm volatile(
                    "cp.async.bulk.shared::cluster.global.mbarrier::complete_tx::bytes "
                    "[%0], [%1], %2, [%3];"
                    :: "r"(hs_u32 + ch * 32768u), "l"(src + ch * 32768),
                       "r"(32768u), "r"(mbb + ch * 8) : "memory");
            }
        }

        // ---- xproj loads (DRAM, independent of h) ---------------------------
        const bool active = t < sl;
        float4 xr, xz, xn;
        if (active) {
            size_t base = ((size_t)b_mine * T_ + t) * G3 + c * HC + ubase;
            xr = __ldcg((const float4*)&g_xproj[base]);
            xz = __ldcg((const float4*)&g_xproj[base + H_]);
            xn = __ldcg((const float4*)&g_xproj[base + 2 * H_]);
        }

        float acc[4][3][4];
#pragma unroll
        for (int mt = 0; mt < 4; mt++)
#pragma unroll
            for (int nt = 0; nt < 3; nt++)
#pragma unroll
                for (int j = 0; j < 4; j++) acc[mt][nt][j] = 0.f;

        // ---- wait for my chunk, then sync-free 16-kt mma loop ---------------
        mbar_wait_parity(mb_q, ph);
#pragma unroll
        for (int kt2 = 0; kt2 < 16; kt2++) {
#pragma unroll
            for (int mt = 0; mt < 4; mt++) {
                unsigned a0, a1, a2, a3;
                asm volatile("ld.shared.v4.u32 {%0,%1,%2,%3}, [%4];"
                             : "=r"(a0), "=r"(a1), "=r"(a2), "=r"(a3)
                             : "r"(abase + (unsigned)((kt2 * 4 + mt) * 512)));
                mma_bf16(acc[mt][0], a0, a1, a2, a3, wb0[kt2][0], wb1[kt2][0]);
                mma_bf16(acc[mt][1], a0, a1, a2, a3, wb0[kt2][1], wb1[kt2][1]);
                mma_bf16(acc[mt][2], a0, a1, a2, a3, wb0[kt2][2], wb1[kt2][2]);
            }
        }

        // ---- dump partials to hpq[q][row][col] -------------------------------
        {
            float* hq = hpq + q * (64 * 52);
            int r0  = (lane >> 2);
            int col = nh * 24 + ((lane & 3) << 1);
#pragma unroll
            for (int mt = 0; mt < 4; mt++) {
#pragma unroll
                for (int nt = 0; nt < 3; nt++) {
                    int cc = col + nt * 8;
                    *(float2*)&hq[(mt * 16 + r0) * 52 + cc] =
                        make_float2(acc[mt][nt][0], acc[mt][nt][1]);
                    *(float2*)&hq[(mt * 16 + r0 + 8) * 52 + cc] =
                        make_float2(acc[mt][nt][2], acc[mt][nt][3]);
                }
            }
        }
        __syncthreads();

        // ---- pointwise GRU update (fp32 carry), summing 4 q-partials ---------
        if (active) {
            const float xrv[4] = {xr.x, xr.y, xr.z, xr.w};
            const float xzv[4] = {xz.x, xz.y, xz.z, xz.w};
            const float xnv[4] = {xn.x, xn.y, xn.z, xn.w};
            const int rowoff = b_mine * 52;
#pragma unroll
            for (int j = 0; j < 4; j++) {
                int u = ubase + j;
                float hr = 0.f, hz = 0.f, hn = 0.f;
#pragma unroll
                for (int qq = 0; qq < 4; qq++) {
                    const float* hq = hpq + qq * (64 * 52) + rowoff;
                    hr += hq[u];
                    hz += hq[16 + u];
                    hn += hq[32 + u];
                }
                float r = sigf(xrv[j] + hr + bh[0][j]);
                float z = sigf(xzv[j] + hz + bh[1][j]);
                float n = tanhf(xnv[j] + r * (hn + bh[2][j]));
                hv[j] = (1.0f - z) * n + z * hv[j];
            }
        }
        // write h (bf16, fragment order) for next step's GEMM
        {
            __nv_bfloat162 w0 = __floats2bfloat162_rn(hv[0], hv[1]);
            __nv_bfloat162 w1 = __floats2bfloat162_rn(hv[2], hv[3]);
            unsigned u0 = *reinterpret_cast<unsigned*>(&w0);
            unsigned u1 = *reinterpret_cast<unsigned*>(&w1);
            unsigned* p = &g_hf[wb][fo];
            asm volatile("st.global.cg.u32 [%0], %1;" :: "l"(p), "r"(u0));
            asm volatile("st.global.cg.u32 [%0], %1;" :: "l"(p + 4), "r"(u1));
        }

        grid_sync_dev();
    }

    // ---- head: out[b] = sigmoid(h[b] . W_out + b_out) ------------------------
    float part = 0.f;
#pragma unroll
    for (int j = 0; j < 4; j++)
        part += hv[j] * W_out[c * HC + ubase + j];
    part += __shfl_down_sync(0xffffffffu, part, 1);
    part += __shfl_down_sync(0xffffffffu, part, 2);
    if ((tid & 3) == 0) atomicAdd(&g_acc[b_mine], part);

    grid_sync_dev();

    if (c == 0 && tid < B_) {
        float v = __ldcg(&g_acc[tid]);
        out[tid] = 1.0f / (1.0f + expf(-(v + b_out[0])));
    }
}

// ---------------------------------------------------------------------------
// Launch
// ---------------------------------------------------------------------------
extern "C" void kernel_launch(void* const* d_in, const int* in_sizes, int n_in,
                              void* d_out, int out_size)
{
    const float* input  = (const float*)d_in[0];
    const int*   seqlen = (const int*)  d_in[1];
    const float* W_ih   = (const float*)d_in[2];
    const float* W_hh   = (const float*)d_in[3];
    const float* b_ih   = (const float*)d_in[4];
    const float* b_hh   = (const float*)d_in[5];
    const float* W_out  = (const float*)d_in[6];
    const float* b_out  = (const float*)d_in[7];
    float* out = (float*)d_out;

    const int SMEM1 = 2 * 2 * 128 * 36 * (int)sizeof(float);   // 73728 B

    cudaFuncSetAttribute(xproj_kernel, cudaFuncAttributeMaxDynamicSharedMemorySize, SMEM1);
    cudaFuncSetAttribute(gru_kernel,   cudaFuncAttributeMaxDynamicSharedMemorySize, SMEM2);

    xproj_kernel<<<dim3(24, 256), 256, SMEM1>>>(input, W_ih, b_ih, seqlen);
    gru_kernel<<<NCTA, 256, SMEM2>>>(seqlen, W_hh, b_hh, W_out, b_out, out);
}

// round 6
// speedup vs baseline: 1.4069x; 1.2321x over previous
#include <cuda_runtime.h>
#include <cuda_bf16.h>
#include <cstdint>

#define B_   64
#define T_   512
#define E_   512
#define H_   1024
#define G3   3072
#define NCTA 128      // gru CTAs
#define HC   8        // hidden units per CTA

// Single extern shared symbol for the whole TU.
extern __shared__ unsigned char smem_raw[];

// ---------------------------------------------------------------------------
// Device scratch (zero-initialized at load; no runtime allocation)
// ---------------------------------------------------------------------------
__device__ float g_xproj[(size_t)B_ * T_ * G3];              // input projections
__device__ __align__(128) unsigned g_hf[2][32768];           // ping-pong h, A-fragment order
__device__ float    g_acc[B_];                               // head partials
__device__ unsigned g_cnt;                                   // barrier counter
__device__ unsigned g_gen;                                   // barrier generation

// ---------------------------------------------------------------------------
// Helpers
// ---------------------------------------------------------------------------
__device__ __forceinline__ void mma_bf16(float* c, unsigned a0, unsigned a1,
                                         unsigned a2, unsigned a3,
                                         unsigned b0, unsigned b1) {
    asm volatile(
        "mma.sync.aligned.m16n8k16.row.col.f32.bf16.bf16.f32 "
        "{%0,%1,%2,%3}, {%4,%5,%6,%7}, {%8,%9}, {%0,%1,%2,%3};\n"
        : "+f"(c[0]), "+f"(c[1]), "+f"(c[2]), "+f"(c[3])
        : "r"(a0), "r"(a1), "r"(a2), "r"(a3), "r"(b0), "r"(b1));
}

__device__ __forceinline__ float sigf(float x) {
    return 1.0f / (1.0f + __expf(-x));
}

__device__ __forceinline__ unsigned bf2u(float a, float b) {
    __nv_bfloat162 p = __floats2bfloat162_rn(a, b);
    return *reinterpret_cast<unsigned*>(&p);
}

// Grid barrier: acq/rel atomics only (no membar.gl / L1 flush).
__device__ __forceinline__ void grid_sync_dev() {
    __syncthreads();
    if (threadIdx.x == 0) {
        unsigned my;
        asm volatile("ld.acquire.gpu.global.u32 %0, [%1];"
                     : "=r"(my) : "l"(&g_gen));
        unsigned a;
        asm volatile("atom.acq_rel.gpu.global.add.u32 %0, [%1], 1;"
                     : "=r"(a) : "l"(&g_cnt));
        if (a == NCTA - 1) {
            asm volatile("st.relaxed.gpu.global.u32 [%0], 0;" :: "l"(&g_cnt));
            asm volatile("red.release.gpu.global.add.u32 [%0], 1;" :: "l"(&g_gen));
        } else {
            unsigned cur;
            do {
                asm volatile("ld.acquire.gpu.global.u32 %0, [%1];"
                             : "=r"(cur) : "l"(&g_gen));
            } while (cur == my);
        }
    }
    __syncthreads();
}

__device__ __forceinline__ void mbar_wait_parity(unsigned mbar, unsigned phase) {
    unsigned done;
    do {
        asm volatile(
            "{\n\t.reg .pred p;\n\t"
            "mbarrier.try_wait.parity.acquire.cta.shared::cta.b64 p, [%1], %2, 0x989680;\n\t"
            "selp.b32 %0, 1, 0, p;\n\t}"
            : "=r"(done) : "r"(mbar), "r"(phase) : "memory");
    } while (!done);
}

// ---------------------------------------------------------------------------
// Phase 1: x_proj = input @ W_ih^T + b_ih   (bf16 mma m16n8k16)
// 128x128 tiles, K=512 in 16 chunks of 32, double-buffered bf16 staging.
// ---------------------------------------------------------------------------
#define XS_STRIDE 20   // u32 per row (16 data + 4 pad)

__global__ void __launch_bounds__(256)
xproj_kernel(const float* __restrict__ A, const float* __restrict__ W,
             const float* __restrict__ bih, const int* __restrict__ seqlen)
{
    const int tm = blockIdx.y, tn = blockIdx.x;
    const int b  = (tm << 7) >> 9;
    const int t0 = (tm << 7) & 511;
    if (t0 >= seqlen[b]) return;

    unsigned* As = (unsigned*)smem_raw;                 // [2][128][20]
    unsigned* Bs = As + 2 * 128 * XS_STRIDE;            // [2][128][20]

    const int tid  = threadIdx.x;
    const int lane = tid & 31, wid = tid >> 5;
    const int warpM = wid >> 2, warpN = wid & 3;
    const int tc = lane & 3, tr = lane >> 2;

    const float* Ag = A + (size_t)(tm * 128) * E_;
    const float* Bg = W + (size_t)(tn * 128) * E_;

    float acc[4][4][4];
#pragma unroll
    for (int i = 0; i < 4; i++)
#pragma unroll
        for (int j = 0; j < 4; j++)
#pragma unroll
            for (int k = 0; k < 4; k++) acc[i][j][k] = 0.0f;

    // load K-chunk 0 into buffer 0
#pragma unroll
    for (int i = 0; i < 4; i++) {
        int f = tid + i * 256;
        int r = f >> 3, c4 = (f & 7) << 2;
        float4 va = *(const float4*)(Ag + (size_t)r * E_ + c4);
        float4 vb = *(const float4*)(Bg + (size_t)r * E_ + c4);
        As[r * XS_STRIDE + (c4 >> 1)]     = bf2u(va.x, va.y);
        As[r * XS_STRIDE + (c4 >> 1) + 1] = bf2u(va.z, va.w);
        Bs[r * XS_STRIDE + (c4 >> 1)]     = bf2u(vb.x, vb.y);
        Bs[r * XS_STRIDE + (c4 >> 1) + 1] = bf2u(vb.z, vb.w);
    }
    __syncthreads();

    for (int ko = 0; ko < 16; ko++) {
        float4 pa[4], pb[4];
        if (ko < 15) {
            int kb = (ko + 1) * 32;
#pragma unroll
            for (int i = 0; i < 4; i++) {
                int f = tid + i * 256;
                int r = f >> 3, c4 = (f & 7) << 2;
                pa[i] = *(const float4*)(Ag + (size_t)r * E_ + kb + c4);
                pb[i] = *(const float4*)(Bg + (size_t)r * E_ + kb + c4);
            }
        }
        const unsigned* Ab = As + (ko & 1) * 128 * XS_STRIDE;
        const unsigned* Bb = Bs + (ko & 1) * 128 * XS_STRIDE;
#pragma unroll
        for (int kk2 = 0; kk2 < 2; kk2++) {
            const int base = kk2 * 8 + tc;
            unsigned a[4][4];
#pragma unroll
            for (int mt = 0; mt < 4; mt++) {
                int r = warpM * 64 + mt * 16 + tr;
                a[mt][0] = Ab[r * XS_STRIDE + base];
                a[mt][1] = Ab[(r + 8) * XS_STRIDE + base];
                a[mt][2] = Ab[r * XS_STRIDE + base + 4];
                a[mt][3] = Ab[(r + 8) * XS_STRIDE + base + 4];
            }
#pragma unroll
            for (int nt = 0; nt < 4; nt++) {
                int n = warpN * 32 + nt * 8 + tr;
                unsigned b0 = Bb[n * XS_STRIDE + base];
                unsigned b1 = Bb[n * XS_STRIDE + base + 4];
#pragma unroll
                for (int mt = 0; mt < 4; mt++)
                    mma_bf16(acc[mt][nt], a[mt][0], a[mt][1], a[mt][2], a[mt][3], b0, b1);
            }
        }
        if (ko < 15) {
            unsigned* Ad = As + ((ko + 1) & 1) * 128 * XS_STRIDE;
            unsigned* Bd = Bs + ((ko + 1) & 1) * 128 * XS_STRIDE;
#pragma unroll
            for (int i = 0; i < 4; i++) {
                int f = tid + i * 256;
                int r = f >> 3, c4 = (f & 7) << 2;
                Ad[r * XS_STRIDE + (c4 >> 1)]     = bf2u(pa[i].x, pa[i].y);
                Ad[r * XS_STRIDE + (c4 >> 1) + 1] = bf2u(pa[i].z, pa[i].w);
                Bd[r * XS_STRIDE + (c4 >> 1)]     = bf2u(pb[i].x, pb[i].y);
                Bd[r * XS_STRIDE + (c4 >> 1) + 1] = bf2u(pb[i].z, pb[i].w);
            }
        }
        __syncthreads();
    }

    // epilogue: + b_ih, store
#pragma unroll
    for (int nt = 0; nt < 4; nt++) {
        int cg = tn * 128 + warpN * 32 + nt * 8 + 2 * tc;
        float bv0 = bih[cg], bv1 = bih[cg + 1];
#pragma unroll
        for (int mt = 0; mt < 4; mt++) {
            int rg = tm * 128 + warpM * 64 + mt * 16 + tr;
            float2 v0 = make_float2(acc[mt][nt][0] + bv0, acc[mt][nt][1] + bv1);
            float2 v1 = make_float2(acc[mt][nt][2] + bv0, acc[mt][nt][3] + bv1);
            *(float2*)&g_xproj[(size_t)rg * G3 + cg]       = v0;
            *(float2*)&g_xproj[(size_t)(rg + 8) * G3 + cg] = v1;
        }
    }
}

// ---------------------------------------------------------------------------
// Phase 2: persistent GRU, 128 CTAs x 256 thr, HC=8 units per CTA.
// W_hh B-fragments in registers (48 u32/thread; warp q owns kt q*8..q*8+7,
// all 24 N-cols; gate == nt). h broadcast: 8x16KB bulk copies + 8 mbarriers;
// warp q waits only chunk q. Partials reduced across 8 q via SMEM hpq.
// ---------------------------------------------------------------------------
#define HPQOFF  131072
#define MBAROFF (131072 + 57344)
#define SMEM2   (131072 + 57344 + 64)
#define HPS     28       // hpq row stride (floats)

__global__ void __launch_bounds__(256, 1)
gru_kernel(const int* __restrict__ seqlen, const float* __restrict__ W_hh,
           const float* __restrict__ b_hh, const float* __restrict__ W_out,
           const float* __restrict__ b_out, float* __restrict__ out)
{
    unsigned char* smem = smem_raw;
    float* hpq = (float*)(smem + HPQOFF);       // [8][64][HPS] partial C

    const int c    = blockIdx.x;
    const int tid  = threadIdx.x;
    const int lane = tid & 31, wid = tid >> 5;
    const int q    = wid;                        // kt chunk 0..7
    const int tc = lane & 3, tr = lane >> 2;

    const unsigned smem_u32 = (unsigned)__cvta_generic_to_shared(smem);
    const unsigned hs_u32   = smem_u32;                    // A stage (128KB)
    const unsigned mbb      = smem_u32 + MBAROFF;          // 8 mbarriers

    // ---- init mbarriers ----------------------------------------------------
    if (tid == 0) {
#pragma unroll
        for (int ch = 0; ch < 8; ch++)
            asm volatile("mbarrier.init.shared.b64 [%0], 1;"
                         :: "r"(mbb + ch * 8) : "memory");
        asm volatile("fence.proxy.async.shared::cta;" ::: "memory");
    }

    // ---- load W_hh B-fragments into registers ------------------------------
    // warp q, lane: fragments for kt = q*8+kt2, nt(=gate) 0..2, n-col tr
    unsigned wb0[8][3], wb1[8][3];
#pragma unroll
    for (int nt = 0; nt < 3; nt++) {
        const float* wr = W_hh + (size_t)(nt * H_ + c * HC + tr) * H_;
#pragma unroll
        for (int kt2 = 0; kt2 < 8; kt2++) {
            int k0 = (q * 8 + kt2) * 16 + tc * 2;
            wb0[kt2][nt] = bf2u(wr[k0],     wr[k0 + 1]);
            wb1[kt2][nt] = bf2u(wr[k0 + 8], wr[k0 + 9]);
        }
    }

    // ---- pointwise identity: batch b_mine, 2 consecutive units -------------
    const int b_mine = tid >> 2;
    const int ub2    = (tid & 3) << 1;          // unit base within CTA: 0,2,4,6
    const int sl     = seqlen[b_mine];
    float bh[3][2];
#pragma unroll
    for (int g = 0; g < 3; g++) {
        bh[g][0] = b_hh[g * H_ + c * HC + ub2];
        bh[g][1] = b_hh[g * H_ + c * HC + ub2 + 1];
    }
    float hv[2] = {0.f, 0.f};

    // fragment-slot offset (u32 units) this thread writes each step
    const int r_b    = b_mine & 15;
    const int mt_b   = b_mine >> 4;
    const int u16    = (c & 1) * 8 + ub2;
    const int lane_b = ((r_b & 7) << 2) | (ub2 >> 1);
    const int reg_b  = ((c & 1) ? 2 : 0) + (r_b >> 3);
    const int kt_b   = c >> 1;
    const unsigned fo = (((unsigned)(kt_b * 4 + mt_b) * 32 + lane_b) << 2) + reg_b;
    (void)u16;

    // zero my slot of frag buffer 0; zero head accumulators
    {
        unsigned* p = &g_hf[0][fo];
        asm volatile("st.global.cg.u32 [%0], 0;" :: "l"(p));
    }
    if (c == 0 && tid < B_) g_acc[tid] = 0.f;

    grid_sync_dev();

    // A-stage read base for this warp: addr = ((kt*4+mt)*32+lane)*16
    const unsigned abase = hs_u32 + (unsigned)(q * 16384 + lane * 16);
    const unsigned mb_q  = mbb + q * 8;

    for (int t = 0; t < T_; t++) {
        const int rb = t & 1, wb = rb ^ 1;
        const unsigned ph = (unsigned)(t & 1);

        // ---- issue chunked bulk h broadcast (8 x 16KB) ----------------------
        if (tid == 0) {
            const char* src = (const char*)&g_hf[rb][0];
            asm volatile("fence.proxy.async;" ::: "memory");
#pragma unroll
            for (int ch = 0; ch < 8; ch++) {
                asm volatile("mbarrier.arrive.expect_tx.shared.b64 _, [%0], %1;"
                             :: "r"(mbb + ch * 8), "r"(16384u) : "memory");
                asm volatile(
                    "cp.async.bulk.shared::cluster.global.mbarrier::complete_tx::bytes "
                    "[%0], [%1], %2, [%3];"
                    :: "r"(hs_u32 + ch * 16384u), "l"(src + ch * 16384),
                       "r"(16384u), "r"(mbb + ch * 8) : "memory");
            }
        }

        // ---- xproj loads (DRAM, independent of h) ---------------------------
        const bool active = t < sl;
        float2 xr, xz, xn;
        if (active) {
            size_t base = ((size_t)b_mine * T_ + t) * G3 + c * HC + ub2;
            xr = __ldcg((const float2*)&g_xproj[base]);
            xz = __ldcg((const float2*)&g_xproj[base + H_]);
            xn = __ldcg((const float2*)&g_xproj[base + 2 * H_]);
        }

        float acc[4][3][4];
#pragma unroll
        for (int mt = 0; mt < 4; mt++)
#pragma unroll
            for (int nt = 0; nt < 3; nt++)
#pragma unroll
                for (int j = 0; j < 4; j++) acc[mt][nt][j] = 0.f;

        // ---- wait for my chunk, then sync-free 8-kt mma loop -----------------
        mbar_wait_parity(mb_q, ph);
#pragma unroll
        for (int kt2 = 0; kt2 < 8; kt2++) {
#pragma unroll
            for (int mt = 0; mt < 4; mt++) {
                unsigned a0, a1, a2, a3;
                asm volatile("ld.shared.v4.u32 {%0,%1,%2,%3}, [%4];"
                             : "=r"(a0), "=r"(a1), "=r"(a2), "=r"(a3)
                             : "r"(abase + (unsigned)((kt2 * 4 + mt) * 512)));
                mma_bf16(acc[mt][0], a0, a1, a2, a3, wb0[kt2][0], wb1[kt2][0]);
                mma_bf16(acc[mt][1], a0, a1, a2, a3, wb0[kt2][1], wb1[kt2][1]);
                mma_bf16(acc[mt][2], a0, a1, a2, a3, wb0[kt2][2], wb1[kt2][2]);
            }
        }

        // ---- dump partials to hpq[q][row][col] -------------------------------
        {
            float* hq = hpq + q * (64 * HPS);
            int col = (tc << 1);
#pragma unroll
            for (int mt = 0; mt < 4; mt++) {
#pragma unroll
                for (int nt = 0; nt < 3; nt++) {
                    int cc = col + nt * 8;
                    *(float2*)&hq[(mt * 16 + tr) * HPS + cc] =
                        make_float2(acc[mt][nt][0], acc[mt][nt][1]);
                    *(float2*)&hq[(mt * 16 + tr + 8) * HPS + cc] =
                        make_float2(acc[mt][nt][2], acc[mt][nt][3]);
                }
            }
        }
        __syncthreads();

        // ---- pointwise GRU update (fp32 carry), summing 8 q-partials ---------
        if (active) {
            float hr0 = 0.f, hr1 = 0.f, hz0 = 0.f, hz1 = 0.f, hn0 = 0.f, hn1 = 0.f;
            const int rowoff = b_mine * HPS + ub2;
#pragma unroll
            for (int qq = 0; qq < 8; qq++) {
                const float* hq = hpq + qq * (64 * HPS) + rowoff;
                float2 vr = *(const float2*)&hq[0];
                float2 vz = *(const float2*)&hq[8];
                float2 vn = *(const float2*)&hq[16];
                hr0 += vr.x; hr1 += vr.y;
                hz0 += vz.x; hz1 += vz.y;
                hn0 += vn.x; hn1 += vn.y;
            }
            {
                float r = sigf(xr.x + hr0 + bh[0][0]);
                float z = sigf(xz.x + hz0 + bh[1][0]);
                float n = tanhf(xn.x + r * (hn0 + bh[2][0]));
                hv[0] = (1.0f - z) * n + z * hv[0];
            }
            {
                float r = sigf(xr.y + hr1 + bh[0][1]);
                float z = sigf(xz.y + hz1 + bh[1][1]);
                float n = tanhf(xn.y + r * (hn1 + bh[2][1]));
                hv[1] = (1.0f - z) * n + z * hv[1];
            }
        }
        // write h (bf16x2, fragment order) for next step's GEMM
        {
            unsigned u0 = bf2u(hv[0], hv[1]);
            unsigned* p = &g_hf[wb][fo];
            asm volatile("st.global.cg.u32 [%0], %1;" :: "l"(p), "r"(u0));
        }

        grid_sync_dev();
    }

    // ---- head: out[b] = sigmoid(h[b] . W_out + b_out) ------------------------
    float part = hv[0] * W_out[c * HC + ub2] + hv[1] * W_out[c * HC + ub2 + 1];
    part += __shfl_down_sync(0xffffffffu, part, 1);
    part += __shfl_down_sync(0xffffffffu, part, 2);
    if ((tid & 3) == 0) atomicAdd(&g_acc[b_mine], part);

    grid_sync_dev();

    if (c == 0 && tid < B_) {
        float v = __ldcg(&g_acc[tid]);
        out[tid] = 1.0f / (1.0f + expf(-(v + b_out[0])));
    }
}

// ---------------------------------------------------------------------------
// Launch
// ---------------------------------------------------------------------------
extern "C" void kernel_launch(void* const* d_in, const int* in_sizes, int n_in,
                              void* d_out, int out_size)
{
    const float* input  = (const float*)d_in[0];
    const int*   seqlen = (const int*)  d_in[1];
    const float* W_ih   = (const float*)d_in[2];
    const float* W_hh   = (const float*)d_in[3];
    const float* b_ih   = (const float*)d_in[4];
    const float* b_hh   = (const float*)d_in[5];
    const float* W_out  = (const float*)d_in[6];
    const float* b_out  = (const float*)d_in[7];
    float* out = (float*)d_out;

    const int SMEM1 = 2 * 2 * 128 * XS_STRIDE * (int)sizeof(unsigned);  // 40960 B

    cudaFuncSetAttribute(xproj_kernel, cudaFuncAttributeMaxDynamicSharedMemorySize, SMEM1);
    cudaFuncSetAttribute(gru_kernel,   cudaFuncAttributeMaxDynamicSharedMemorySize, SMEM2);

    xproj_kernel<<<dim3(24, 256), 256, SMEM1>>>(input, W_ih, b_ih, seqlen);
    gru_kernel<<<NCTA, 256, SMEM2>>>(seqlen, W_hh, b_hh, W_out, b_out, out);
}

// round 8
// speedup vs baseline: 1.5399x; 1.0945x over previous
#include <cuda_runtime.h>
#include <cuda_bf16.h>
#include <cstdint>

#define B_   64
#define T_   512
#define E_   512
#define H_   1024
#define G3   3072
#define NCTA 128      // gru CTAs
#define HC   8        // hidden units per CTA

// Single extern shared symbol for the whole TU.
extern __shared__ unsigned char smem_raw[];

// ---------------------------------------------------------------------------
// Device scratch (zero-initialized at load; no runtime allocation)
// ---------------------------------------------------------------------------
__device__ float g_xproj[(size_t)B_ * T_ * G3];              // input projections
__device__ __align__(128) unsigned g_hf[2][32768];           // ping-pong h, A-fragment order
__device__ float    g_acc[B_];                               // head partials
__device__ unsigned g_ready[8];                              // per-chunk version counters
__device__ unsigned g_cnt;                                   // barrier counter
__device__ unsigned g_gen;                                   // barrier generation

// ---------------------------------------------------------------------------
// Helpers
// ---------------------------------------------------------------------------
__device__ __forceinline__ void mma_bf16(float* c, unsigned a0, unsigned a1,
                                         unsigned a2, unsigned a3,
                                         unsigned b0, unsigned b1) {
    asm volatile(
        "mma.sync.aligned.m16n8k16.row.col.f32.bf16.bf16.f32 "
        "{%0,%1,%2,%3}, {%4,%5,%6,%7}, {%8,%9}, {%0,%1,%2,%3};\n"
        : "+f"(c[0]), "+f"(c[1]), "+f"(c[2]), "+f"(c[3])
        : "r"(a0), "r"(a1), "r"(a2), "r"(a3), "r"(b0), "r"(b1));
}

__device__ __forceinline__ float sigf(float x) {
    return 1.0f / (1.0f + __expf(-x));
}

__device__ __forceinline__ unsigned bf2u(float a, float b) {
    __nv_bfloat162 p = __floats2bfloat162_rn(a, b);
    return *reinterpret_cast<unsigned*>(&p);
}

// Grid barrier (init + final only): acq/rel atomics, no membar.gl.
__device__ __forceinline__ void grid_sync_dev() {
    __syncthreads();
    if (threadIdx.x == 0) {
        unsigned my;
        asm volatile("ld.acquire.gpu.global.u32 %0, [%1];"
                     : "=r"(my) : "l"(&g_gen));
        unsigned a;
        asm volatile("atom.acq_rel.gpu.global.add.u32 %0, [%1], 1;"
                     : "=r"(a) : "l"(&g_cnt));
        if (a == NCTA - 1) {
            asm volatile("st.relaxed.gpu.global.u32 [%0], 0;" :: "l"(&g_cnt));
            asm volatile("red.release.gpu.global.add.u32 [%0], 1;" :: "l"(&g_gen));
        } else {
            unsigned cur;
            do {
                asm volatile("ld.acquire.gpu.global.u32 %0, [%1];"
                             : "=r"(cur) : "l"(&g_gen));
            } while (cur == my);
        }
    }
    __syncthreads();
}

__device__ __forceinline__ void mbar_wait_parity(unsigned mbar, unsigned phase) {
    unsigned done;
    do {
        asm volatile(
            "{\n\t.reg .pred p;\n\t"
            "mbarrier.try_wait.parity.acquire.cta.shared::cta.b64 p, [%1], %2, 0x989680;\n\t"
            "selp.b32 %0, 1, 0, p;\n\t}"
            : "=r"(done) : "r"(mbar), "r"(phase) : "memory");
    } while (!done);
}

// ---------------------------------------------------------------------------
// Phase 1: x_proj = input @ W_ih^T + b_ih   (bf16 mma m16n8k16, unchanged)
// ---------------------------------------------------------------------------
#define XS_STRIDE 20   // u32 per row (16 data + 4 pad)

__global__ void __launch_bounds__(256)
xproj_kernel(const float* __restrict__ A, const float* __restrict__ W,
             const float* __restrict__ bih, const int* __restrict__ seqlen)
{
    const int tm = blockIdx.y, tn = blockIdx.x;
    const int b  = (tm << 7) >> 9;
    const int t0 = (tm << 7) & 511;
    if (t0 >= seqlen[b]) return;

    unsigned* As = (unsigned*)smem_raw;                 // [2][128][20]
    unsigned* Bs = As + 2 * 128 * XS_STRIDE;            // [2][128][20]

    const int tid  = threadIdx.x;
    const int lane = tid & 31, wid = tid >> 5;
    const int warpM = wid >> 2, warpN = wid & 3;
    const int tc = lane & 3, tr = lane >> 2;

    const float* Ag = A + (size_t)(tm * 128) * E_;
    const float* Bg = W + (size_t)(tn * 128) * E_;

    float acc[4][4][4];
#pragma unroll
    for (int i = 0; i < 4; i++)
#pragma unroll
        for (int j = 0; j < 4; j++)
#pragma unroll
            for (int k = 0; k < 4; k++) acc[i][j][k] = 0.0f;

#pragma unroll
    for (int i = 0; i < 4; i++) {
        int f = tid + i * 256;
        int r = f >> 3, c4 = (f & 7) << 2;
        float4 va = *(const float4*)(Ag + (size_t)r * E_ + c4);
        float4 vb = *(const float4*)(Bg + (size_t)r * E_ + c4);
        As[r * XS_STRIDE + (c4 >> 1)]     = bf2u(va.x, va.y);
        As[r * XS_STRIDE + (c4 >> 1) + 1] = bf2u(va.z, va.w);
        Bs[r * XS_STRIDE + (c4 >> 1)]     = bf2u(vb.x, vb.y);
        Bs[r * XS_STRIDE + (c4 >> 1) + 1] = bf2u(vb.z, vb.w);
    }
    __syncthreads();

    for (int ko = 0; ko < 16; ko++) {
        float4 pa[4], pb[4];
        if (ko < 15) {
            int kb = (ko + 1) * 32;
#pragma unroll
            for (int i = 0; i < 4; i++) {
                int f = tid + i * 256;
                int r = f >> 3, c4 = (f & 7) << 2;
                pa[i] = *(const float4*)(Ag + (size_t)r * E_ + kb + c4);
                pb[i] = *(const float4*)(Bg + (size_t)r * E_ + kb + c4);
            }
        }
        const unsigned* Ab = As + (ko & 1) * 128 * XS_STRIDE;
        const unsigned* Bb = Bs + (ko & 1) * 128 * XS_STRIDE;
#pragma unroll
        for (int kk2 = 0; kk2 < 2; kk2++) {
            const int base = kk2 * 8 + tc;
            unsigned a[4][4];
#pragma unroll
            for (int mt = 0; mt < 4; mt++) {
                int r = warpM * 64 + mt * 16 + tr;
                a[mt][0] = Ab[r * XS_STRIDE + base];
                a[mt][1] = Ab[(r + 8) * XS_STRIDE + base];
                a[mt][2] = Ab[r * XS_STRIDE + base + 4];
                a[mt][3] = Ab[(r + 8) * XS_STRIDE + base + 4];
            }
#pragma unroll
            for (int nt = 0; nt < 4; nt++) {
                int n = warpN * 32 + nt * 8 + tr;
                unsigned b0 = Bb[n * XS_STRIDE + base];
                unsigned b1 = Bb[n * XS_STRIDE + base + 4];
#pragma unroll
                for (int mt = 0; mt < 4; mt++)
                    mma_bf16(acc[mt][nt], a[mt][0], a[mt][1], a[mt][2], a[mt][3], b0, b1);
            }
        }
        if (ko < 15) {
            unsigned* Ad = As + ((ko + 1) & 1) * 128 * XS_STRIDE;
            unsigned* Bd = Bs + ((ko + 1) & 1) * 128 * XS_STRIDE;
#pragma unroll
            for (int i = 0; i < 4; i++) {
                int f = tid + i * 256;
                int r = f >> 3, c4 = (f & 7) << 2;
                Ad[r * XS_STRIDE + (c4 >> 1)]     = bf2u(pa[i].x, pa[i].y);
                Ad[r * XS_STRIDE + (c4 >> 1) + 1] = bf2u(pa[i].z, pa[i].w);
                Bd[r * XS_STRIDE + (c4 >> 1)]     = bf2u(pb[i].x, pb[i].y);
                Bd[r * XS_STRIDE + (c4 >> 1) + 1] = bf2u(pb[i].z, pb[i].w);
            }
        }
        __syncthreads();
    }

#pragma unroll
    for (int nt = 0; nt < 4; nt++) {
        int cg = tn * 128 + warpN * 32 + nt * 8 + 2 * tc;
        float bv0 = bih[cg], bv1 = bih[cg + 1];
#pragma unroll
        for (int mt = 0; mt < 4; mt++) {
            int rg = tm * 128 + warpM * 64 + mt * 16 + tr;
            float2 v0 = make_float2(acc[mt][nt][0] + bv0, acc[mt][nt][1] + bv1);
            float2 v1 = make_float2(acc[mt][nt][2] + bv0, acc[mt][nt][3] + bv1);
            *(float2*)&g_xproj[(size_t)rg * G3 + cg]       = v0;
            *(float2*)&g_xproj[(size_t)(rg + 8) * G3 + cg] = v1;
        }
    }
}

// ---------------------------------------------------------------------------
// Phase 2: persistent GRU, 128 CTAs x 256 thr, HC=8. NO clusters.
// Dataflow sync: per-chunk monotone counters g_ready[8]. Chunk ch produced by
// CTAs [16ch,16ch+16). Warp q (per CTA) polls ready[q] >= 16*(t+1), then
// issues its own 16KB bulk copy -> its own mbarrier -> mma. No per-step grid
// barrier. W_hh B-fragments in registers.
// ---------------------------------------------------------------------------
#define HPQOFF  131072
#define MBAROFF (131072 + 57344)
#define SMEM2   (131072 + 57344 + 64)
#define HPS     28       // hpq row stride (floats)

__global__ void __launch_bounds__(256, 1)
gru_kernel(const int* __restrict__ seqlen, const float* __restrict__ W_hh,
           const float* __restrict__ b_hh, const float* __restrict__ W_out,
           const float* __restrict__ b_out, float* __restrict__ out)
{
    unsigned char* smem = smem_raw;
    float* hpq = (float*)(smem + HPQOFF);       // [8][64][HPS] partial C

    const int c    = blockIdx.x;
    const int tid  = threadIdx.x;
    const int lane = tid & 31, wid = tid >> 5;
    const int q    = wid;                        // kt chunk 0..7
    const int tc = lane & 3, tr = lane >> 2;
    const int mych = c >> 4;                     // chunk this CTA produces

    const unsigned smem_u32 = (unsigned)__cvta_generic_to_shared(smem);
    const unsigned hs_u32   = smem_u32;                    // A stage (128KB)
    const unsigned mbb      = smem_u32 + MBAROFF;          // 8 mbarriers

    // ---- reset ready counters (replay safety) + init mbarriers --------------
    if (c == 0 && tid < 8)
        asm volatile("st.relaxed.gpu.global.u32 [%0], 0;" :: "l"(&g_ready[tid]));
    if (tid == 0) {
#pragma unroll
        for (int ch = 0; ch < 8; ch++)
            asm volatile("mbarrier.init.shared.b64 [%0], 1;"
                         :: "r"(mbb + ch * 8) : "memory");
        asm volatile("fence.proxy.async.shared::cta;" ::: "memory");
    }

    // ---- load W_hh B-fragments into registers ------------------------------
    unsigned wb0[8][3], wb1[8][3];
#pragma unroll
    for (int nt = 0; nt < 3; nt++) {
        const float* wr = W_hh + (size_t)(nt * H_ + c * HC + tr) * H_;
#pragma unroll
        for (int kt2 = 0; kt2 < 8; kt2++) {
            int k0 = (q * 8 + kt2) * 16 + tc * 2;
            wb0[kt2][nt] = bf2u(wr[k0],     wr[k0 + 1]);
            wb1[kt2][nt] = bf2u(wr[k0 + 8], wr[k0 + 9]);
        }
    }

    // ---- pointwise identity: batch b_mine, 2 consecutive units -------------
    const int b_mine = tid >> 2;
    const int ub2    = (tid & 3) << 1;
    const int sl     = seqlen[b_mine];
    float bh[3][2];
#pragma unroll
    for (int g = 0; g < 3; g++) {
        bh[g][0] = b_hh[g * H_ + c * HC + ub2];
        bh[g][1] = b_hh[g * H_ + c * HC + ub2 + 1];
    }
    float hv[2] = {0.f, 0.f};

    // fragment-slot offset (u32 units) this thread writes each step
    const int r_b    = b_mine & 15;
    const int mt_b   = b_mine >> 4;
    const int lane_b = ((r_b & 7) << 2) | (ub2 >> 1);
    const int reg_b  = ((c & 1) ? 2 : 0) + (r_b >> 3);
    const int kt_b   = c >> 1;
    const unsigned fo = (((unsigned)(kt_b * 4 + mt_b) * 32 + lane_b) << 2) + reg_b;

    // zero my slot of frag buffer 0 (h version 0); zero head accumulators
    {
        unsigned* p = &g_hf[0][fo];
        asm volatile("st.global.cg.u32 [%0], 0;" :: "l"(p));
    }
    if (c == 0 && tid < B_) g_acc[tid] = 0.f;

    // orders: counter resets, version-0 stores, mbar inits across the grid
    grid_sync_dev();

    // announce version 0
    if (tid == 0)
        asm volatile("red.release.gpu.global.add.u32 [%0], 1;"
                     :: "l"(&g_ready[mych]));

    const unsigned abase = hs_u32 + (unsigned)(q * 16384 + lane * 16);
    const unsigned mb_q  = mbb + q * 8;

    for (int t = 0; t < T_; t++) {
        const int rb = t & 1, wb = rb ^ 1;
        const unsigned ph = (unsigned)(t & 1);

        // ---- warp q: wait chunk-q producers, issue own 16KB bulk copy -------
        if (lane == 0) {
            const unsigned target = 16u * (unsigned)(t + 1);
            unsigned v;
            do {
                asm volatile("ld.relaxed.gpu.global.u32 %0, [%1];"
                             : "=r"(v) : "l"(&g_ready[q]));
            } while (v < target);
            asm volatile("fence.proxy.async;" ::: "memory");
            asm volatile("mbarrier.arrive.expect_tx.shared.b64 _, [%0], %1;"
                         :: "r"(mb_q), "r"(16384u) : "memory");
            const char* src = (const char*)&g_hf[rb][0] + q * 16384u;
            asm volatile(
                "cp.async.bulk.shared::cluster.global.mbarrier::complete_tx::bytes "
                "[%0], [%1], %2, [%3];"
                :: "r"(hs_u32 + q * 16384u), "l"(src), "r"(16384u), "r"(mb_q)
                : "memory");
        }

        // ---- xproj loads (DRAM, independent of h) ---------------------------
        const bool active = t < sl;
        float2 xr, xz, xn;
        if (active) {
            size_t base = ((size_t)b_mine * T_ + t) * G3 + c * HC + ub2;
            xr = __ldcg((const float2*)&g_xproj[base]);
            xz = __ldcg((const float2*)&g_xproj[base + H_]);
            xn = __ldcg((const float2*)&g_xproj[base + 2 * H_]);
        }

        float acc[4][3][4];
#pragma unroll
        for (int mt = 0; mt < 4; mt++)
#pragma unroll
            for (int nt = 0; nt < 3; nt++)
#pragma unroll
                for (int j = 0; j < 4; j++) acc[mt][nt][j] = 0.f;

        // ---- wait my chunk landed, mma -------------------------------------
        mbar_wait_parity(mb_q, ph);
#pragma unroll
        for (int kt2 = 0; kt2 < 8; kt2++) {
#pragma unroll
            for (int mt = 0; mt < 4; mt++) {
                unsigned a0, a1, a2, a3;
                asm volatile("ld.shared.v4.u32 {%0,%1,%2,%3}, [%4];"
                             : "=r"(a0), "=r"(a1), "=r"(a2), "=r"(a3)
                             : "r"(abase + (unsigned)((kt2 * 4 + mt) * 512)));
                mma_bf16(acc[mt][0], a0, a1, a2, a3, wb0[kt2][0], wb1[kt2][0]);
                mma_bf16(acc[mt][1], a0, a1, a2, a3, wb0[kt2][1], wb1[kt2][1]);
                mma_bf16(acc[mt][2], a0, a1, a2, a3, wb0[kt2][2], wb1[kt2][2]);
            }
        }

        // ---- dump partials to hpq[q][row][col] -------------------------------
        {
            float* hq = hpq + q * (64 * HPS);
            int col = (tc << 1);
#pragma unroll
            for (int mt = 0; mt < 4; mt++) {
#pragma unroll
                for (int nt = 0; nt < 3; nt++) {
                    int cc = col + nt * 8;
                    *(float2*)&hq[(mt * 16 + tr) * HPS + cc] =
                        make_float2(acc[mt][nt][0], acc[mt][nt][1]);
                    *(float2*)&hq[(mt * 16 + tr + 8) * HPS + cc] =
                        make_float2(acc[mt][nt][2], acc[mt][nt][3]);
                }
            }
        }
        __syncthreads();

        // ---- pointwise GRU update (fp32 carry), summing 8 q-partials ---------
        if (active) {
            float hr0 = 0.f, hr1 = 0.f, hz0 = 0.f, hz1 = 0.f, hn0 = 0.f, hn1 = 0.f;
            const int rowoff = b_mine * HPS + ub2;
#pragma unroll
            for (int qq = 0; qq < 8; qq++) {
                const float* hq = hpq + qq * (64 * HPS) + rowoff;
                float2 vr = *(const float2*)&hq[0];
                float2 vz = *(const float2*)&hq[8];
                float2 vn = *(const float2*)&hq[16];
                hr0 += vr.x; hr1 += vr.y;
                hz0 += vz.x; hz1 += vz.y;
                hn0 += vn.x; hn1 += vn.y;
            }
            {
                float r = sigf(xr.x + hr0 + bh[0][0]);
                float z = sigf(xz.x + hz0 + bh[1][0]);
                float n = tanhf(xn.x + r * (hn0 + bh[2][0]));
                hv[0] = (1.0f - z) * n + z * hv[0];
            }
            {
                float r = sigf(xr.y + hr1 + bh[0][1]);
                float z = sigf(xz.y + hz1 + bh[1][1]);
                float n = tanhf(xn.y + r * (hn1 + bh[2][1]));
                hv[1] = (1.0f - z) * n + z * hv[1];
            }
        }
        // write h version t+1 (bf16x2, fragment order)
        {
            unsigned u0 = bf2u(hv[0], hv[1]);
            unsigned* p = &g_hf[wb][fo];
            asm volatile("st.global.cg.u32 [%0], %1;" :: "l"(p), "r"(u0));
        }
        __syncthreads();   // all h stores issued; hpq reads done before next dump

        // announce version t+1
        if (tid == 0)
            asm volatile("red.release.gpu.global.add.u32 [%0], 1;"
                         :: "l"(&g_ready[mych]));
    }

    // ---- head: out[b] = sigmoid(h[b] . W_out + b_out) ------------------------
    float part = hv[0] * W_out[c * HC + ub2] + hv[1] * W_out[c * HC + ub2 + 1];
    part += __shfl_down_sync(0xffffffffu, part, 1);
    part += __shfl_down_sync(0xffffffffu, part, 2);
    if ((tid & 3) == 0) atomicAdd(&g_acc[b_mine], part);

    grid_sync_dev();

    if (c == 0 && tid < B_) {
        float v = __ldcg(&g_acc[tid]);
        out[tid] = 1.0f / (1.0f + expf(-(v + b_out[0])));
    }
}

// ---------------------------------------------------------------------------
// Launch
// ---------------------------------------------------------------------------
extern "C" void kernel_launch(void* const* d_in, const int* in_sizes, int n_in,
                              void* d_out, int out_size)
{
    const float* input  = (const float*)d_in[0];
    const int*   seqlen = (const int*)  d_in[1];
    const float* W_ih   = (const float*)d_in[2];
    const float* W_hh   = (const float*)d_in[3];
    const float* b_ih   = (const float*)d_in[4];
    const float* b_hh   = (const float*)d_in[5];
    const float* W_out  = (const float*)d_in[6];
    const float* b_out  = (const float*)d_in[7];
    float* out = (float*)d_out;

    const int SMEM1 = 2 * 2 * 128 * XS_STRIDE * (int)sizeof(unsigned);  // 40960 B

    cudaFuncSetAttribute(xproj_kernel, cudaFuncAttributeMaxDynamicSharedMemorySize, SMEM1);
    cudaFuncSetAttribute(gru_kernel,   cudaFuncAttributeMaxDynamicSharedMemorySize, SMEM2);

    xproj_kernel<<<dim3(24, 256), 256, SMEM1>>>(input, W_ih, b_ih, seqlen);
    gru_kernel<<<NCTA, 256, SMEM2>>>(seqlen, W_hh, b_hh, W_out, b_out, out);
}

// round 9
// speedup vs baseline: 1.8291x; 1.1878x over previous
#include <cuda_runtime.h>
#include <cuda_bf16.h>
#include <cstdint>

#define B_   64
#define T_   512
#define E_   512
#define H_   1024
#define G3   3072
#define NCTA 128      // gru CTAs
#define HC   8        // hidden units per CTA

// Single extern shared symbol for the whole TU.
extern __shared__ unsigned char smem_raw[];

// ---------------------------------------------------------------------------
// Device scratch (zero-initialized at load; no runtime allocation)
// ---------------------------------------------------------------------------
__device__ float g_xproj[(size_t)B_ * T_ * G3];              // input projections
__device__ __align__(128) unsigned g_hf[2][32768];           // ping-pong h, A-fragment order
__device__ float    g_acc[B_];                               // head partials
__device__ unsigned g_ready[8];                              // per-chunk version counters
__device__ unsigned g_cnt;                                   // barrier counter
__device__ unsigned g_gen;                                   // barrier generation

// ---------------------------------------------------------------------------
// Helpers
// ---------------------------------------------------------------------------
__device__ __forceinline__ void mma_bf16(float* c, unsigned a0, unsigned a1,
                                         unsigned a2, unsigned a3,
                                         unsigned b0, unsigned b1) {
    asm volatile(
        "mma.sync.aligned.m16n8k16.row.col.f32.bf16.bf16.f32 "
        "{%0,%1,%2,%3}, {%4,%5,%6,%7}, {%8,%9}, {%0,%1,%2,%3};\n"
        : "+f"(c[0]), "+f"(c[1]), "+f"(c[2]), "+f"(c[3])
        : "r"(a0), "r"(a1), "r"(a2), "r"(a3), "r"(b0), "r"(b1));
}

__device__ __forceinline__ float sigf(float x) {
    return 1.0f / (1.0f + __expf(-x));
}

__device__ __forceinline__ unsigned bf2u(float a, float b) {
    __nv_bfloat162 p = __floats2bfloat162_rn(a, b);
    return *reinterpret_cast<unsigned*>(&p);
}

// Grid barrier (init + final only): acq/rel atomics, no membar.gl.
__device__ __forceinline__ void grid_sync_dev() {
    __syncthreads();
    if (threadIdx.x == 0) {
        unsigned my;
        asm volatile("ld.acquire.gpu.global.u32 %0, [%1];"
                     : "=r"(my) : "l"(&g_gen));
        unsigned a;
        asm volatile("atom.acq_rel.gpu.global.add.u32 %0, [%1], 1;"
                     : "=r"(a) : "l"(&g_cnt));
        if (a == NCTA - 1) {
            asm volatile("st.relaxed.gpu.global.u32 [%0], 0;" :: "l"(&g_cnt));
            asm volatile("red.release.gpu.global.add.u32 [%0], 1;" :: "l"(&g_gen));
        } else {
            unsigned cur;
            do {
                asm volatile("ld.acquire.gpu.global.u32 %0, [%1];"
                             : "=r"(cur) : "l"(&g_gen));
            } while (cur == my);
        }
    }
    __syncthreads();
}

// ---------------------------------------------------------------------------
// Phase 1: x_proj = input @ W_ih^T + b_ih   (bf16 mma m16n8k16, unchanged)
// ---------------------------------------------------------------------------
#define XS_STRIDE 20   // u32 per row (16 data + 4 pad)

__global__ void __launch_bounds__(256)
xproj_kernel(const float* __restrict__ A, const float* __restrict__ W,
             const float* __restrict__ bih, const int* __restrict__ seqlen)
{
    const int tm = blockIdx.y, tn = blockIdx.x;
    const int b  = (tm << 7) >> 9;
    const int t0 = (tm << 7) & 511;
    if (t0 >= seqlen[b]) return;

    unsigned* As = (unsigned*)smem_raw;                 // [2][128][20]
    unsigned* Bs = As + 2 * 128 * XS_STRIDE;            // [2][128][20]

    const int tid  = threadIdx.x;
    const int lane = tid & 31, wid = tid >> 5;
    const int warpM = wid >> 2, warpN = wid & 3;
    const int tc = lane & 3, tr = lane >> 2;

    const float* Ag = A + (size_t)(tm * 128) * E_;
    const float* Bg = W + (size_t)(tn * 128) * E_;

    float acc[4][4][4];
#pragma unroll
    for (int i = 0; i < 4; i++)
#pragma unroll
        for (int j = 0; j < 4; j++)
#pragma unroll
            for (int k = 0; k < 4; k++) acc[i][j][k] = 0.0f;

#pragma unroll
    for (int i = 0; i < 4; i++) {
        int f = tid + i * 256;
        int r = f >> 3, c4 = (f & 7) << 2;
        float4 va = *(const float4*)(Ag + (size_t)r * E_ + c4);
        float4 vb = *(const float4*)(Bg + (size_t)r * E_ + c4);
        As[r * XS_STRIDE + (c4 >> 1)]     = bf2u(va.x, va.y);
        As[r * XS_STRIDE + (c4 >> 1) + 1] = bf2u(va.z, va.w);
        Bs[r * XS_STRIDE + (c4 >> 1)]     = bf2u(vb.x, vb.y);
        Bs[r * XS_STRIDE + (c4 >> 1) + 1] = bf2u(vb.z, vb.w);
    }
    __syncthreads();

    for (int ko = 0; ko < 16; ko++) {
        float4 pa[4], pb[4];
        if (ko < 15) {
            int kb = (ko + 1) * 32;
#pragma unroll
            for (int i = 0; i < 4; i++) {
                int f = tid + i * 256;
                int r = f >> 3, c4 = (f & 7) << 2;
                pa[i] = *(const float4*)(Ag + (size_t)r * E_ + kb + c4);
                pb[i] = *(const float4*)(Bg + (size_t)r * E_ + kb + c4);
            }
        }
        const unsigned* Ab = As + (ko & 1) * 128 * XS_STRIDE;
        const unsigned* Bb = Bs + (ko & 1) * 128 * XS_STRIDE;
#pragma unroll
        for (int kk2 = 0; kk2 < 2; kk2++) {
            const int base = kk2 * 8 + tc;
            unsigned a[4][4];
#pragma unroll
            for (int mt = 0; mt < 4; mt++) {
                int r = warpM * 64 + mt * 16 + tr;
                a[mt][0] = Ab[r * XS_STRIDE + base];
                a[mt][1] = Ab[(r + 8) * XS_STRIDE + base];
                a[mt][2] = Ab[r * XS_STRIDE + base + 4];
                a[mt][3] = Ab[(r + 8) * XS_STRIDE + base + 4];
            }
#pragma unroll
            for (int nt = 0; nt < 4; nt++) {
                int n = warpN * 32 + nt * 8 + tr;
                unsigned b0 = Bb[n * XS_STRIDE + base];
                unsigned b1 = Bb[n * XS_STRIDE + base + 4];
#pragma unroll
                for (int mt = 0; mt < 4; mt++)
                    mma_bf16(acc[mt][nt], a[mt][0], a[mt][1], a[mt][2], a[mt][3], b0, b1);
            }
        }
        if (ko < 15) {
            unsigned* Ad = As + ((ko + 1) & 1) * 128 * XS_STRIDE;
            unsigned* Bd = Bs + ((ko + 1) & 1) * 128 * XS_STRIDE;
#pragma unroll
            for (int i = 0; i < 4; i++) {
                int f = tid + i * 256;
                int r = f >> 3, c4 = (f & 7) << 2;
                Ad[r * XS_STRIDE + (c4 >> 1)]     = bf2u(pa[i].x, pa[i].y);
                Ad[r * XS_STRIDE + (c4 >> 1) + 1] = bf2u(pa[i].z, pa[i].w);
                Bd[r * XS_STRIDE + (c4 >> 1)]     = bf2u(pb[i].x, pb[i].y);
                Bd[r * XS_STRIDE + (c4 >> 1) + 1] = bf2u(pb[i].z, pb[i].w);
            }
        }
        __syncthreads();
    }

#pragma unroll
    for (int nt = 0; nt < 4; nt++) {
        int cg = tn * 128 + warpN * 32 + nt * 8 + 2 * tc;
        float bv0 = bih[cg], bv1 = bih[cg + 1];
#pragma unroll
        for (int mt = 0; mt < 4; mt++) {
            int rg = tm * 128 + warpM * 64 + mt * 16 + tr;
            float2 v0 = make_float2(acc[mt][nt][0] + bv0, acc[mt][nt][1] + bv1);
            float2 v1 = make_float2(acc[mt][nt][2] + bv0, acc[mt][nt][3] + bv1);
            *(float2*)&g_xproj[(size_t)rg * G3 + cg]       = v0;
            *(float2*)&g_xproj[(size_t)(rg + 8) * G3 + cg] = v1;
        }
    }
}

// ---------------------------------------------------------------------------
// Phase 2: persistent GRU, 128 CTAs x 256 thr, HC=8.
// NO TMA / NO SMEM staging: mma A-operands loaded directly from L2 with
// ld.global.cg.v4 (fragment layout in g_hf == mma A layout, fully coalesced),
// double-buffered over kt2 so L2 latency overlaps mma. Sync: per-chunk
// monotone counters (all-lane acquire poll). W_hh B-fragments in registers.
// ---------------------------------------------------------------------------
#define SMEM2 (57344 + 64)
#define HPS   28       // hpq row stride (floats)

__global__ void __launch_bounds__(256, 1)
gru_kernel(const int* __restrict__ seqlen, const float* __restrict__ W_hh,
           const float* __restrict__ b_hh, const float* __restrict__ W_out,
           const float* __restrict__ b_out, float* __restrict__ out)
{
    float* hpq = (float*)smem_raw;              // [8][64][HPS] partial C

    const int c    = blockIdx.x;
    const int tid  = threadIdx.x;
    const int lane = tid & 31, wid = tid >> 5;
    const int q    = wid;                        // kt chunk 0..7
    const int tc = lane & 3, tr = lane >> 2;
    const int mych = c >> 4;                     // chunk this CTA produces

    // ---- reset ready counters (replay safety) -------------------------------
    if (c == 0 && tid < 8)
        asm volatile("st.relaxed.gpu.global.u32 [%0], 0;" :: "l"(&g_ready[tid]));

    // ---- load W_hh B-fragments into registers ------------------------------
    unsigned wb0[8][3], wb1[8][3];
#pragma unroll
    for (int nt = 0; nt < 3; nt++) {
        const float* wr = W_hh + (size_t)(nt * H_ + c * HC + tr) * H_;
#pragma unroll
        for (int kt2 = 0; kt2 < 8; kt2++) {
            int k0 = (q * 8 + kt2) * 16 + tc * 2;
            wb0[kt2][nt] = bf2u(wr[k0],     wr[k0 + 1]);
            wb1[kt2][nt] = bf2u(wr[k0 + 8], wr[k0 + 9]);
        }
    }

    // ---- pointwise identity: batch b_mine, 2 consecutive units -------------
    const int b_mine = tid >> 2;
    const int ub2    = (tid & 3) << 1;
    const int sl     = seqlen[b_mine];
    float bh[3][2];
#pragma unroll
    for (int g = 0; g < 3; g++) {
        bh[g][0] = b_hh[g * H_ + c * HC + ub2];
        bh[g][1] = b_hh[g * H_ + c * HC + ub2 + 1];
    }
    float hv[2] = {0.f, 0.f};

    // fragment-slot offset (u32 units) this thread writes each step
    const int r_b    = b_mine & 15;
    const int mt_b   = b_mine >> 4;
    const int lane_b = ((r_b & 7) << 2) | (ub2 >> 1);
    const int reg_b  = ((c & 1) ? 2 : 0) + (r_b >> 3);
    const int kt_b   = c >> 1;
    const unsigned fo = (((unsigned)(kt_b * 4 + mt_b) * 32 + lane_b) << 2) + reg_b;

    // zero my slot of frag buffer 0 (h version 0); zero head accumulators
    {
        unsigned* p = &g_hf[0][fo];
        asm volatile("st.global.cg.u32 [%0], 0;" :: "l"(p));
    }
    if (c == 0 && tid < B_) g_acc[tid] = 0.f;

    // orders: counter resets + version-0 stores across the grid
    grid_sync_dev();

    // announce version 0
    if (tid == 0)
        asm volatile("red.release.gpu.global.add.u32 [%0], 1;"
                     :: "l"(&g_ready[mych]));

    // per-thread A-operand base (u32 units) inside my chunk
    const unsigned aoff = (unsigned)(q * 4096 + lane * 4);

    for (int t = 0; t < T_; t++) {
        const int rb = t & 1, wb = rb ^ 1;

        // ---- xproj loads (DRAM, independent of h) ---------------------------
        const bool active = t < sl;
        float2 xr, xz, xn;
        if (active) {
            size_t base = ((size_t)b_mine * T_ + t) * G3 + c * HC + ub2;
            xr = __ldcg((const float2*)&g_xproj[base]);
            xz = __ldcg((const float2*)&g_xproj[base + H_]);
            xn = __ldcg((const float2*)&g_xproj[base + 2 * H_]);
        }

        // ---- all lanes: acquire-poll chunk-q producers -----------------------
        {
            const unsigned target = 16u * (unsigned)(t + 1);
            unsigned v;
            do {
                asm volatile("ld.acquire.gpu.global.u32 %0, [%1];"
                             : "=r"(v) : "l"(&g_ready[q]));
            } while (v < target);
        }

        const unsigned* hb = &g_hf[rb][0] + aoff;

        float acc[4][3][4];
#pragma unroll
        for (int mt = 0; mt < 4; mt++)
#pragma unroll
            for (int nt = 0; nt < 3; nt++)
#pragma unroll
                for (int j = 0; j < 4; j++) acc[mt][nt][j] = 0.f;

        // ---- direct-from-L2 mma loop, double-buffered over kt2 ---------------
        unsigned af[2][4][4];
#pragma unroll
        for (int mt = 0; mt < 4; mt++)
            asm volatile("ld.global.cg.v4.u32 {%0,%1,%2,%3}, [%4];"
                         : "=r"(af[0][mt][0]), "=r"(af[0][mt][1]),
                           "=r"(af[0][mt][2]), "=r"(af[0][mt][3])
                         : "l"(hb + mt * 128));
#pragma unroll
        for (int kt2 = 0; kt2 < 8; kt2++) {
            const int cur = kt2 & 1, nxt = cur ^ 1;
            if (kt2 < 7) {
#pragma unroll
                for (int mt = 0; mt < 4; mt++)
                    asm volatile("ld.global.cg.v4.u32 {%0,%1,%2,%3}, [%4];"
                                 : "=r"(af[nxt][mt][0]), "=r"(af[nxt][mt][1]),
                                   "=r"(af[nxt][mt][2]), "=r"(af[nxt][mt][3])
                                 : "l"(hb + ((kt2 + 1) * 4 + mt) * 128));
            }
#pragma unroll
            for (int mt = 0; mt < 4; mt++) {
                mma_bf16(acc[mt][0], af[cur][mt][0], af[cur][mt][1],
                         af[cur][mt][2], af[cur][mt][3], wb0[kt2][0], wb1[kt2][0]);
                mma_bf16(acc[mt][1], af[cur][mt][0], af[cur][mt][1],
                         af[cur][mt][2], af[cur][mt][3], wb0[kt2][1], wb1[kt2][1]);
                mma_bf16(acc[mt][2], af[cur][mt][0], af[cur][mt][1],
                         af[cur][mt][2], af[cur][mt][3], wb0[kt2][2], wb1[kt2][2]);
            }
        }

        // ---- dump partials to hpq[q][row][col] -------------------------------
        {
            float* hq = hpq + q * (64 * HPS);
            int col = (tc << 1);
#pragma unroll
            for (int mt = 0; mt < 4; mt++) {
#pragma unroll
                for (int nt = 0; nt < 3; nt++) {
                    int cc = col + nt * 8;
                    *(float2*)&hq[(mt * 16 + tr) * HPS + cc] =
                        make_float2(acc[mt][nt][0], acc[mt][nt][1]);
                    *(float2*)&hq[(mt * 16 + tr + 8) * HPS + cc] =
                        make_float2(acc[mt][nt][2], acc[mt][nt][3]);
                }
            }
        }
        __syncthreads();

        // ---- pointwise GRU update (fp32 carry), summing 8 q-partials ---------
        if (active) {
            float hr0 = 0.f, hr1 = 0.f, hz0 = 0.f, hz1 = 0.f, hn0 = 0.f, hn1 = 0.f;
            const int rowoff = b_mine * HPS + ub2;
#pragma unroll
            for (int qq = 0; qq < 8; qq++) {
                const float* hq = hpq + qq * (64 * HPS) + rowoff;
                float2 vr = *(const float2*)&hq[0];
                float2 vz = *(const float2*)&hq[8];
                float2 vn = *(const float2*)&hq[16];
                hr0 += vr.x; hr1 += vr.y;
                hz0 += vz.x; hz1 += vz.y;
                hn0 += vn.x; hn1 += vn.y;
            }
            {
                float r = sigf(xr.x + hr0 + bh[0][0]);
                float z = sigf(xz.x + hz0 + bh[1][0]);
                float n = tanhf(xn.x + r * (hn0 + bh[2][0]));
                hv[0] = (1.0f - z) * n + z * hv[0];
            }
            {
                float r = sigf(xr.y + hr1 + bh[0][1]);
                float z = sigf(xz.y + hz1 + bh[1][1]);
                float n = tanhf(xn.y + r * (hn1 + bh[2][1]));
                hv[1] = (1.0f - z) * n + z * hv[1];
            }
        }
        // write h version t+1 (bf16x2, fragment order)
        {
            unsigned u0 = bf2u(hv[0], hv[1]);
            unsigned* p = &g_hf[wb][fo];
            asm volatile("st.global.cg.u32 [%0], %1;" :: "l"(p), "r"(u0));
        }
        __syncthreads();   // all h stores issued before announce

        // announce version t+1
        if (tid == 0)
            asm volatile("red.release.gpu.global.add.u32 [%0], 1;"
                         :: "l"(&g_ready[mych]));
    }

    // ---- head: out[b] = sigmoid(h[b] . W_out + b_out) ------------------------
    float part = hv[0] * W_out[c * HC + ub2] + hv[1] * W_out[c * HC + ub2 + 1];
    part += __shfl_down_sync(0xffffffffu, part, 1);
    part += __shfl_down_sync(0xffffffffu, part, 2);
    if ((tid & 3) == 0) atomicAdd(&g_acc[b_mine], part);

    grid_sync_dev();

    if (c == 0 && tid < B_) {
        float v = __ldcg(&g_acc[tid]);
        out[tid] = 1.0f / (1.0f + expf(-(v + b_out[0])));
    }
}

// ---------------------------------------------------------------------------
// Launch
// ---------------------------------------------------------------------------
extern "C" void kernel_launch(void* const* d_in, const int* in_sizes, int n_in,
                              void* d_out, int out_size)
{
    const float* input  = (const float*)d_in[0];
    const int*   seqlen = (const int*)  d_in[1];
    const float* W_ih   = (const float*)d_in[2];
    const float* W_hh   = (const float*)d_in[3];
    const float* b_ih   = (const float*)d_in[4];
    const float* b_hh   = (const float*)d_in[5];
    const float* W_out  = (const float*)d_in[6];
    const float* b_out  = (const float*)d_in[7];
    float* out = (float*)d_out;

    const int SMEM1 = 2 * 2 * 128 * XS_STRIDE * (int)sizeof(unsigned);  // 40960 B

    cudaFuncSetAttribute(xproj_kernel, cudaFuncAttributeMaxDynamicSharedMemorySize, SMEM1);
    cudaFuncSetAttribute(gru_kernel,   cudaFuncAttributeMaxDynamicSharedMemorySize, SMEM2);

    xproj_kernel<<<dim3(24, 256), 256, SMEM1>>>(input, W_ih, b_ih, seqlen);
    gru_kernel<<<NCTA, 256, SMEM2>>>(seqlen, W_hh, b_hh, W_out, b_out, out);
}